// round 1
// baseline (speedup 1.0000x reference)
#include <cuda_runtime.h>
#include <cuda_bf16.h>
#include <math.h>

#define H_ 768
#define N_ 16
#define NLAYERS 6
#define NOUTS 38
#define BATCH 8
#define LMAX 2048

#define MAXACT (BATCH*LMAX*H_)

__device__ float g_A [MAXACT];
__device__ float g_Bf[MAXACT];
__device__ float g_U [MAXACT];
__device__ float g_YT[MAXACT];
__device__ float g_Y [MAXACT];
__device__ float g_V [BATCH*LMAX*2*H_];

// ---------------------------------------------------------------------------
// Encoder stage 1: T[row, j] = softsign(x_raw[row,:8] @ W1[:, j] + b1[j])
// ---------------------------------------------------------------------------
__global__ void enc1_kernel(const float* __restrict__ xr,
                            const float* __restrict__ w1,
                            const float* __restrict__ b1,
                            float* __restrict__ T) {
    int row = blockIdx.x;
    __shared__ float xs[8];
    if (threadIdx.x < 8) xs[threadIdx.x] = xr[(size_t)row * 8 + threadIdx.x];
    __syncthreads();
    for (int j = threadIdx.x; j < H_; j += blockDim.x) {
        float s = b1[j];
#pragma unroll
        for (int k = 0; k < 8; ++k) s = fmaf(xs[k], w1[k * H_ + j], s);
        T[(size_t)row * H_ + j] = s / (1.0f + fabsf(s));
    }
}

// ---------------------------------------------------------------------------
// SGEMM: C[M,N] = A[M,K] @ op(B) + bias[N]
//   BT=false: B is (K,N) row-major (NN)
//   BT=true : B is (N,K) row-major (NT)
// Requires M%128==0, N%128==0, K%8==0, K%4==0. 256 threads, 128x128 tile.
// ---------------------------------------------------------------------------
template <bool BT>
__global__ void sgemm_kernel(const float* __restrict__ A,
                             const float* __restrict__ B,
                             const float* __restrict__ bias,
                             float* __restrict__ C,
                             int M, int N, int K) {
    __shared__ float As[8][128];
    __shared__ float Bs[8][128];

    const int tid = threadIdx.x;
    const int tx = tid & 15;        // 0..15  -> col frag
    const int ty = tid >> 4;        // 0..15  -> row frag
    const int bx = blockIdx.x;      // N tile
    const int by = blockIdx.y;      // M tile

    // global load mapping (A and NT-B): 128 rows x 8 k, float4 along k
    const int la_r = tid >> 1;            // 0..127
    const int la_c = (tid & 1) * 4;       // 0 or 4
    // NN-B mapping: 8 k-rows x 128 n, float4 along n
    const int lb_k = tid >> 5;            // 0..7
    const int lb_n = (tid & 31) * 4;      // 0..124

    const float* Aptr = A + (size_t)(by * 128 + la_r) * K + la_c;
    const float* Bptr;
    if (BT) Bptr = B + (size_t)(bx * 128 + la_r) * K + la_c;
    else    Bptr = B + (size_t)lb_k * N + bx * 128 + lb_n;

    float acc[8][8];
#pragma unroll
    for (int i = 0; i < 8; ++i)
#pragma unroll
        for (int j = 0; j < 8; ++j) acc[i][j] = 0.0f;

    for (int k0 = 0; k0 < K; k0 += 8) {
        float4 av = *(const float4*)(Aptr + k0);
        As[la_c + 0][la_r] = av.x;
        As[la_c + 1][la_r] = av.y;
        As[la_c + 2][la_r] = av.z;
        As[la_c + 3][la_r] = av.w;
        if (BT) {
            float4 bv = *(const float4*)(Bptr + k0);
            Bs[la_c + 0][la_r] = bv.x;
            Bs[la_c + 1][la_r] = bv.y;
            Bs[la_c + 2][la_r] = bv.z;
            Bs[la_c + 3][la_r] = bv.w;
        } else {
            float4 bv = *(const float4*)(Bptr + (size_t)k0 * N);
            *(float4*)&Bs[lb_k][lb_n] = bv;
        }
        __syncthreads();
#pragma unroll
        for (int kk = 0; kk < 8; ++kk) {
            float4 a0 = *(const float4*)&As[kk][ty * 4];
            float4 a1 = *(const float4*)&As[kk][64 + ty * 4];
            float4 b0 = *(const float4*)&Bs[kk][tx * 4];
            float4 b1 = *(const float4*)&Bs[kk][64 + tx * 4];
            float af[8] = {a0.x, a0.y, a0.z, a0.w, a1.x, a1.y, a1.z, a1.w};
            float bf[8] = {b0.x, b0.y, b0.z, b0.w, b1.x, b1.y, b1.z, b1.w};
#pragma unroll
            for (int i = 0; i < 8; ++i)
#pragma unroll
                for (int j = 0; j < 8; ++j)
                    acc[i][j] = fmaf(af[i], bf[j], acc[i][j]);
        }
        __syncthreads();
    }

    // epilogue
    int ncol0 = bx * 128 + tx * 4;
    float4 bi0, bi1;
    bi0 = *(const float4*)&bias[ncol0];
    bi1 = *(const float4*)&bias[ncol0 + 64];
#pragma unroll
    for (int i = 0; i < 8; ++i) {
        int m = by * 128 + (i < 4 ? ty * 4 + i : 64 + ty * 4 + (i - 4));
        float4 v0, v1;
        v0.x = acc[i][0] + bi0.x; v0.y = acc[i][1] + bi0.y;
        v0.z = acc[i][2] + bi0.z; v0.w = acc[i][3] + bi0.w;
        v1.x = acc[i][4] + bi1.x; v1.y = acc[i][5] + bi1.y;
        v1.z = acc[i][6] + bi1.z; v1.w = acc[i][7] + bi1.w;
        *(float4*)&C[(size_t)m * N + ncol0]      = v0;
        *(float4*)&C[(size_t)m * N + ncol0 + 64] = v1;
    }
}

// ---------------------------------------------------------------------------
// Batched 2D transpose: src (batch, R, C) -> dst (batch, C, R)
// block (32,8), grid (C/32, R/32, batch)
// ---------------------------------------------------------------------------
__global__ void transpose_kernel(float* __restrict__ dst,
                                 const float* __restrict__ src,
                                 int R, int C) {
    __shared__ float tile[32][33];
    size_t boff = (size_t)blockIdx.z * R * C;
    int c0 = blockIdx.x * 32;
    int r0 = blockIdx.y * 32;
    int x = threadIdx.x;
#pragma unroll
    for (int i = threadIdx.y; i < 32; i += 8)
        tile[i][x] = src[boff + (size_t)(r0 + i) * C + c0 + x];
    __syncthreads();
#pragma unroll
    for (int i = threadIdx.y; i < 32; i += 8)
        dst[boff + (size_t)(c0 + i) * R + r0 + x] = tile[x][i];
}

// ---------------------------------------------------------------------------
// Bidirectional diagonal SSM scan + D*u + exact GELU.
// U, Y: (B*H, L). One warp = 2 channels; 16 lanes = 16 complex states.
// ---------------------------------------------------------------------------
__global__ void s4_scan_kernel(const float* __restrict__ U,
                               float* __restrict__ Y,
                               const float* __restrict__ log_dt,
                               const float* __restrict__ log_A_real,
                               const float* __restrict__ A_imag,
                               const float* __restrict__ C_ri,
                               const float* __restrict__ Dv,
                               int L, int layer) {
    int warp = (blockIdx.x * blockDim.x + threadIdx.x) >> 5;
    int lane = threadIdx.x & 31;
    int half = lane >> 4;
    int n    = lane & 15;
    int ch   = warp * 2 + half;          // 0 .. B*H-1
    int h    = ch % H_;

    // --- per-(h,n) coefficients ---
    float dt  = expf(log_dt[layer * H_ + h]);
    int   pidx = (layer * H_ + h) * N_ + n;
    float Are = -expf(log_A_real[pidx]);
    float Aim = A_imag[pidx];
    float dr = dt * Are, di = dt * Aim;
    float e  = expf(dr);
    float ar = e * cosf(di);
    float ai = e * sinf(di);
    float invA2 = 1.0f / (Are * Are + Aim * Aim);
    float dBr = ((ar - 1.0f) * Are + ai * Aim) * invA2;
    float dBi = (ai * Are - (ar - 1.0f) * Aim) * invA2;

    size_t c0idx = ((((size_t)layer * 2 + 0) * H_ + h) * N_ + n) * 2;
    size_t c1idx = ((((size_t)layer * 2 + 1) * H_ + h) * N_ + n) * 2;
    float c0r = C_ri[c0idx], c0i = C_ri[c0idx + 1];
    float c1r = C_ri[c1idx], c1i = C_ri[c1idx + 1];
    float w0r = c0r * dBr - c0i * dBi, w0i = c0r * dBi + c0i * dBr;
    float w1r = c1r * dBr - c1i * dBi, w1i = c1r * dBi + c1i * dBr;

    const float* u = U + (size_t)ch * L;
    float*       y = Y + (size_t)ch * L;
    float Dh = Dv[layer * H_ + h];

    // --- backward pass: y[p] = 2*Re(C1 * s[p]),  s[p] = u[p+1] + a*s[p+1] ---
    float sr = 0.0f, si = 0.0f;
    for (int p = L - 1; p >= 0; --p) {
        float c = w1r * sr - w1i * si;
        c += __shfl_xor_sync(0xffffffffu, c, 8);
        c += __shfl_xor_sync(0xffffffffu, c, 4);
        c += __shfl_xor_sync(0xffffffffu, c, 2);
        c += __shfl_xor_sync(0xffffffffu, c, 1);
        float ul = u[p];
        if (n == 0) y[p] = 2.0f * c;
        float t = fmaf(ar, sr, fmaf(-ai, si, ul));
        si = fmaf(ar, si, ai * sr);
        sr = t;
    }
    // --- forward pass: h = a*h + u;  y = gelu(2*Re(C0*h) + y_bwd + D*u) ---
    float hr = 0.0f, hi = 0.0f;
    for (int l = 0; l < L; ++l) {
        float ul = u[l];
        float t = fmaf(ar, hr, fmaf(-ai, hi, ul));
        hi = fmaf(ar, hi, ai * hr);
        hr = t;
        float c = w0r * hr - w0i * hi;
        c += __shfl_xor_sync(0xffffffffu, c, 8);
        c += __shfl_xor_sync(0xffffffffu, c, 4);
        c += __shfl_xor_sync(0xffffffffu, c, 2);
        c += __shfl_xor_sync(0xffffffffu, c, 1);
        if (n == 0) {
            float yv = 2.0f * c + y[l] + Dh * ul;
            y[l] = 0.5f * yv * (1.0f + erff(yv * 0.70710678118654752f));
        }
    }
}

// ---------------------------------------------------------------------------
// GLU + residual + LayerNorm (+ optional stride-2 downsample).
// V: (M_in, 1536), X: (M_in, 768), out: (M_out, 768). One block per out row.
// ---------------------------------------------------------------------------
__global__ void glu_ln_kernel(const float* __restrict__ V,
                              const float* __restrict__ X,
                              const float* __restrict__ nw,
                              const float* __restrict__ nb,
                              float* __restrict__ out, int ds) {
    int row_out = blockIdx.x;
    int row_in  = ds ? row_out * 2 : row_out;
    const float* v = V + (size_t)row_in * (2 * H_);
    const float* x = X + (size_t)row_in * H_;
    int tid = threadIdx.x;

    float vals[3];
    float s = 0.0f, q = 0.0f;
#pragma unroll
    for (int t = 0; t < 3; ++t) {
        int j = tid + t * 256;
        float a = v[j];
        float g = v[j + H_];
        float z = a * (1.0f / (1.0f + expf(-g)));
        float xr = z + x[j];
        vals[t] = xr;
        s += xr;
        q += xr * xr;
    }
    __shared__ float sh[18];
    int lane = tid & 31, wid = tid >> 5;
#pragma unroll
    for (int o = 16; o; o >>= 1) {
        s += __shfl_xor_sync(0xffffffffu, s, o);
        q += __shfl_xor_sync(0xffffffffu, q, o);
    }
    if (lane == 0) { sh[wid] = s; sh[8 + wid] = q; }
    __syncthreads();
    if (tid == 0) {
        float S = 0.0f, Q = 0.0f;
#pragma unroll
        for (int i = 0; i < 8; ++i) { S += sh[i]; Q += sh[8 + i]; }
        float mu = S * (1.0f / H_);
        float var = Q * (1.0f / H_) - mu * mu;
        sh[16] = mu;
        sh[17] = rsqrtf(var + 1e-5f);
    }
    __syncthreads();
    float mu = sh[16], inv = sh[17];
#pragma unroll
    for (int t = 0; t < 3; ++t) {
        int j = tid + t * 256;
        out[(size_t)row_out * H_ + j] = (vals[t] - mu) * inv * nw[j] + nb[j];
    }
}

// ---------------------------------------------------------------------------
// Head: out[row, d] = X[row,:] @ wout[:, d] + wb[d]
// ---------------------------------------------------------------------------
__global__ void head_kernel(const float* __restrict__ X,
                            const float* __restrict__ W,
                            const float* __restrict__ bb,
                            float* __restrict__ out) {
    int row = blockIdx.x;
    __shared__ float xs[H_];
    for (int j = threadIdx.x; j < H_; j += blockDim.x)
        xs[j] = X[(size_t)row * H_ + j];
    __syncthreads();
    int d = threadIdx.x;
    if (d < NOUTS) {
        float sum = bb[d];
#pragma unroll 4
        for (int k = 0; k < H_; ++k)
            sum = fmaf(xs[k], W[k * NOUTS + d], sum);
        out[(size_t)row * NOUTS + d] = sum;
    }
}

// ---------------------------------------------------------------------------
extern "C" void kernel_launch(void* const* d_in, const int* in_sizes, int n_in,
                              void* d_out, int out_size) {
    const float* x_raw      = (const float*)d_in[1];
    const float* enc_w1     = (const float*)d_in[3];
    const float* enc_b1     = (const float*)d_in[4];
    const float* enc_w2     = (const float*)d_in[5];
    const float* enc_b2     = (const float*)d_in[6];
    const float* log_dt     = (const float*)d_in[7];
    const float* log_A_real = (const float*)d_in[8];
    const float* A_imag     = (const float*)d_in[9];
    const float* C_ri       = (const float*)d_in[10];
    const float* Dv         = (const float*)d_in[11];
    const float* out_w      = (const float*)d_in[12];
    const float* out_b      = (const float*)d_in[13];
    const float* norm_w     = (const float*)d_in[14];
    const float* norm_b     = (const float*)d_in[15];
    const float* wout_w     = (const float*)d_in[16];
    const float* wout_b     = (const float*)d_in[17];

    float *gA, *gB, *gU, *gYT, *gY, *gV;
    cudaGetSymbolAddress((void**)&gA,  g_A);
    cudaGetSymbolAddress((void**)&gB,  g_Bf);
    cudaGetSymbolAddress((void**)&gU,  g_U);
    cudaGetSymbolAddress((void**)&gYT, g_YT);
    cudaGetSymbolAddress((void**)&gY,  g_Y);
    cudaGetSymbolAddress((void**)&gV,  g_V);

    // encoder
    enc1_kernel<<<BATCH * LMAX, 256>>>(x_raw, enc_w1, enc_b1, gY);
    sgemm_kernel<false><<<dim3(H_ / 128, (BATCH * LMAX) / 128), 256>>>(
        gY, enc_w2, enc_b2, gA, BATCH * LMAX, H_, H_);

    int Lcur = LMAX;
    float* cur = gA;
    float* nxt = gB;
    for (int i = 0; i < NLAYERS; ++i) {
        int Mi = BATCH * Lcur;
        // (B, L, H) -> (B, H, L)
        transpose_kernel<<<dim3(H_ / 32, Lcur / 32, BATCH), dim3(32, 8)>>>(
            gU, cur, Lcur, H_);
        // bidirectional scan + gelu, writes (B, H, L)
        s4_scan_kernel<<<(BATCH * H_ / 2) / 8, 256>>>(
            gU, gYT, log_dt, log_A_real, A_imag, C_ri, Dv, Lcur, i);
        // (B, H, L) -> (B, L, H)
        transpose_kernel<<<dim3(Lcur / 32, H_ / 32, BATCH), dim3(32, 8)>>>(
            gY, gYT, H_, Lcur);
        // V = Y @ out_w^T + out_b   (NT)
        sgemm_kernel<true><<<dim3((2 * H_) / 128, Mi / 128), 256>>>(
            gY, out_w + (size_t)i * 2 * H_ * H_, out_b + (size_t)i * 2 * H_,
            gV, Mi, 2 * H_, H_);
        // GLU + residual + LayerNorm (+ downsample on layers 0..2)
        int ds = (i <= 2) ? 1 : 0;
        int Mout = ds ? Mi / 2 : Mi;
        glu_ln_kernel<<<Mout, 256>>>(gV, cur, norm_w + i * H_, norm_b + i * H_,
                                     nxt, ds);
        if (ds) Lcur /= 2;
        float* tmp = cur; cur = nxt; nxt = tmp;
    }

    head_kernel<<<BATCH * Lcur, 128>>>(cur, wout_w, wout_b, (float*)d_out);
}

// round 2
// speedup vs baseline: 1.5012x; 1.5012x over previous
#include <cuda_runtime.h>
#include <cuda_bf16.h>
#include <math.h>

#define H_ 768
#define N_ 16
#define NLAYERS 6
#define NOUTS 38
#define BATCH 8
#define LMAX 2048
#define NC 32          // chunks per sequence for the scan

#define MAXACT (BATCH*LMAX*H_)

__device__ float g_A [MAXACT];
__device__ float g_Bf[MAXACT];
__device__ float g_Y [MAXACT];                 // fwd scan output (compact rows)
__device__ float g_YT[MAXACT];                 // bwd scan output (compact rows)
__device__ float g_V [BATCH*LMAX*2*H_];        // GEMM output
__device__ float g_S [2*BATCH*NC*2*N_*H_];     // chunk states: [dir][b][c][32comp][h]
__device__ float g_CF[8*N_*H_];                // coefs: [comp][n][h]

// ---------------------------------------------------------------------------
// Encoder stage 1: T[row, j] = softsign(x_raw[row,:8] @ W1[:, j] + b1[j])
// ---------------------------------------------------------------------------
__global__ void enc1_kernel(const float* __restrict__ xr,
                            const float* __restrict__ w1,
                            const float* __restrict__ b1,
                            float* __restrict__ T) {
    int row = blockIdx.x;
    __shared__ float xs[8];
    if (threadIdx.x < 8) xs[threadIdx.x] = xr[(size_t)row * 8 + threadIdx.x];
    __syncthreads();
    for (int j = threadIdx.x; j < H_; j += blockDim.x) {
        float s = b1[j];
#pragma unroll
        for (int k = 0; k < 8; ++k) s = fmaf(xs[k], w1[k * H_ + j], s);
        T[(size_t)row * H_ + j] = s / (1.0f + fabsf(s));
    }
}

// ---------------------------------------------------------------------------
// SGEMM: C[M,N] = A[M,K] @ op(B) + bias[N]
// ---------------------------------------------------------------------------
template <bool BT>
__global__ void sgemm_kernel(const float* __restrict__ A,
                             const float* __restrict__ B,
                             const float* __restrict__ bias,
                             float* __restrict__ C,
                             int M, int N, int K) {
    __shared__ float As[8][128];
    __shared__ float Bs[8][128];

    const int tid = threadIdx.x;
    const int tx = tid & 15;
    const int ty = tid >> 4;
    const int bx = blockIdx.x;
    const int by = blockIdx.y;

    const int la_r = tid >> 1;
    const int la_c = (tid & 1) * 4;
    const int lb_k = tid >> 5;
    const int lb_n = (tid & 31) * 4;

    const float* Aptr = A + (size_t)(by * 128 + la_r) * K + la_c;
    const float* Bptr;
    if (BT) Bptr = B + (size_t)(bx * 128 + la_r) * K + la_c;
    else    Bptr = B + (size_t)lb_k * N + bx * 128 + lb_n;

    float acc[8][8];
#pragma unroll
    for (int i = 0; i < 8; ++i)
#pragma unroll
        for (int j = 0; j < 8; ++j) acc[i][j] = 0.0f;

    for (int k0 = 0; k0 < K; k0 += 8) {
        float4 av = *(const float4*)(Aptr + k0);
        As[la_c + 0][la_r] = av.x;
        As[la_c + 1][la_r] = av.y;
        As[la_c + 2][la_r] = av.z;
        As[la_c + 3][la_r] = av.w;
        if (BT) {
            float4 bv = *(const float4*)(Bptr + k0);
            Bs[la_c + 0][la_r] = bv.x;
            Bs[la_c + 1][la_r] = bv.y;
            Bs[la_c + 2][la_r] = bv.z;
            Bs[la_c + 3][la_r] = bv.w;
        } else {
            float4 bv = *(const float4*)(Bptr + (size_t)k0 * N);
            *(float4*)&Bs[lb_k][lb_n] = bv;
        }
        __syncthreads();
#pragma unroll
        for (int kk = 0; kk < 8; ++kk) {
            float4 a0 = *(const float4*)&As[kk][ty * 4];
            float4 a1 = *(const float4*)&As[kk][64 + ty * 4];
            float4 b0 = *(const float4*)&Bs[kk][tx * 4];
            float4 b1 = *(const float4*)&Bs[kk][64 + tx * 4];
            float af[8] = {a0.x, a0.y, a0.z, a0.w, a1.x, a1.y, a1.z, a1.w};
            float bf[8] = {b0.x, b0.y, b0.z, b0.w, b1.x, b1.y, b1.z, b1.w};
#pragma unroll
            for (int i = 0; i < 8; ++i)
#pragma unroll
                for (int j = 0; j < 8; ++j)
                    acc[i][j] = fmaf(af[i], bf[j], acc[i][j]);
        }
        __syncthreads();
    }

    int ncol0 = bx * 128 + tx * 4;
    float4 bi0 = *(const float4*)&bias[ncol0];
    float4 bi1 = *(const float4*)&bias[ncol0 + 64];
#pragma unroll
    for (int i = 0; i < 8; ++i) {
        int m = by * 128 + (i < 4 ? ty * 4 + i : 64 + ty * 4 + (i - 4));
        float4 v0, v1;
        v0.x = acc[i][0] + bi0.x; v0.y = acc[i][1] + bi0.y;
        v0.z = acc[i][2] + bi0.z; v0.w = acc[i][3] + bi0.w;
        v1.x = acc[i][4] + bi1.x; v1.y = acc[i][5] + bi1.y;
        v1.z = acc[i][6] + bi1.z; v1.w = acc[i][7] + bi1.w;
        *(float4*)&C[(size_t)m * N + ncol0]      = v0;
        *(float4*)&C[(size_t)m * N + ncol0 + 64] = v1;
    }
}

// ---------------------------------------------------------------------------
// Per-layer SSM coefficients -> g_CF[comp][n][h]
// comp: 0 ar, 1 ai, 2 w0r, 3 w0i, 4 w1r, 5 w1i, 6 aLr, 7 aLi  (aL = a^CL)
// ---------------------------------------------------------------------------
__global__ void coef_kernel(const float* __restrict__ log_dt,
                            const float* __restrict__ log_A_real,
                            const float* __restrict__ A_imag,
                            const float* __restrict__ C_ri,
                            int layer, int CL) {
    int idx = blockIdx.x * blockDim.x + threadIdx.x;   // 768*16
    int h = idx % H_;
    int n = idx / H_;

    float dt  = expf(log_dt[layer * H_ + h]);
    int pidx  = (layer * H_ + h) * N_ + n;
    float Are = -expf(log_A_real[pidx]);
    float Aim = A_imag[pidx];
    float dr = dt * Are, di = dt * Aim;
    float e  = expf(dr);
    float ar = e * cosf(di);
    float ai = e * sinf(di);
    float invA2 = 1.0f / (Are * Are + Aim * Aim);
    float dBr = ((ar - 1.0f) * Are + ai * Aim) * invA2;
    float dBi = (ai * Are - (ar - 1.0f) * Aim) * invA2;

    size_t c0idx = ((((size_t)layer * 2 + 0) * H_ + h) * N_ + n) * 2;
    size_t c1idx = ((((size_t)layer * 2 + 1) * H_ + h) * N_ + n) * 2;
    float c0r = C_ri[c0idx], c0i = C_ri[c0idx + 1];
    float c1r = C_ri[c1idx], c1i = C_ri[c1idx + 1];

    float eL = expf(CL * dr);
    float aLr = eL * cosf(CL * di);
    float aLi = eL * sinf(CL * di);

    g_CF[(0 * N_ + n) * H_ + h] = ar;
    g_CF[(1 * N_ + n) * H_ + h] = ai;
    g_CF[(2 * N_ + n) * H_ + h] = c0r * dBr - c0i * dBi;
    g_CF[(3 * N_ + n) * H_ + h] = c0r * dBi + c0i * dBr;
    g_CF[(4 * N_ + n) * H_ + h] = c1r * dBr - c1i * dBi;
    g_CF[(5 * N_ + n) * H_ + h] = c1r * dBi + c1i * dBr;
    g_CF[(6 * N_ + n) * H_ + h] = aLr;
    g_CF[(7 * N_ + n) * H_ + h] = aLi;
}

// ---------------------------------------------------------------------------
// Scan pass 1: per-chunk local final states (zero init), both directions.
// X: (B, L, H). grid (3, NC, B*2), block 256. Thread = (h, chunk, b, dir).
// ---------------------------------------------------------------------------
__global__ void scan_pass1(const float* __restrict__ X, int L, int CL) {
    int h   = blockIdx.x * 256 + threadIdx.x;
    int c   = blockIdx.y;
    int bz  = blockIdx.z;
    int b   = bz >> 1;
    int dir = bz & 1;

    float ar[N_], ai[N_], sr[N_], si[N_];
#pragma unroll
    for (int n = 0; n < N_; ++n) {
        ar[n] = g_CF[(0 * N_ + n) * H_ + h];
        ai[n] = g_CF[(1 * N_ + n) * H_ + h];
        sr[n] = 0.0f; si[n] = 0.0f;
    }
    int lo = c * CL;
    if (dir == 0) {
        const float* xp = X + ((size_t)b * L + lo) * H_ + h;
        for (int l = 0; l < CL; ++l) {
            float u = *xp; xp += H_;
#pragma unroll
            for (int n = 0; n < N_; ++n) {
                float t = fmaf(ar[n], sr[n], fmaf(-ai[n], si[n], u));
                si[n] = fmaf(ar[n], si[n], ai[n] * sr[n]);
                sr[n] = t;
            }
        }
    } else {
        const float* xp = X + ((size_t)b * L + lo + CL - 1) * H_ + h;
        for (int l = 0; l < CL; ++l) {
            float u = *xp; xp -= H_;
#pragma unroll
            for (int n = 0; n < N_; ++n) {
                float t = fmaf(ar[n], sr[n], fmaf(-ai[n], si[n], u));
                si[n] = fmaf(ar[n], si[n], ai[n] * sr[n]);
                sr[n] = t;
            }
        }
    }
    float* f = g_S + (((size_t)(dir * BATCH + b) * NC + c) * 32) * H_ + h;
#pragma unroll
    for (int n = 0; n < N_; ++n) {
        f[(2 * n + 0) * H_] = sr[n];
        f[(2 * n + 1) * H_] = si[n];
    }
}

// ---------------------------------------------------------------------------
// Scan fix: compose chunk boundary states serially. Overwrites finals with the
// INIT state entering each chunk. Thread = (dir, b, h, n); 196608 threads.
// ---------------------------------------------------------------------------
__global__ void scan_fix() {
    int idx = blockIdx.x * blockDim.x + threadIdx.x;
    int h   = idx % H_;
    int n   = (idx / H_) % N_;
    int b   = (idx / (H_ * N_)) % BATCH;
    int dir = idx / (H_ * N_ * BATCH);

    float aLr = g_CF[(6 * N_ + n) * H_ + h];
    float aLi = g_CF[(7 * N_ + n) * H_ + h];

    float accr = 0.0f, acci = 0.0f;
    for (int c = 0; c < NC; ++c) {
        int cc = (dir == 0) ? c : (NC - 1 - c);
        float* p = g_S + (((size_t)(dir * BATCH + b) * NC + cc) * 32) * H_ + h;
        float fr = p[(2 * n + 0) * H_];
        float fi = p[(2 * n + 1) * H_];
        p[(2 * n + 0) * H_] = accr;
        p[(2 * n + 1) * H_] = acci;
        float t = aLr * accr - aLi * acci + fr;
        acci = aLr * acci + aLi * accr + fi;
        accr = t;
    }
}

// ---------------------------------------------------------------------------
// Scan pass 2, backward direction: y_bwd[p] = 2*Re(sum_n w1 * s), state
// entering p; then s = a*s + u[p]. Writes COMPACT rows (even p only if ds).
// ---------------------------------------------------------------------------
__global__ void scan_bwd(const float* __restrict__ X, float* __restrict__ Yb,
                         int L, int CL, int Lout, int ds) {
    int h = blockIdx.x * 256 + threadIdx.x;
    int c = blockIdx.y;
    int b = blockIdx.z;

    float ar[N_], ai[N_], wr[N_], wi[N_], sr[N_], si[N_];
    const float* stp = g_S + (((size_t)(1 * BATCH + b) * NC + c) * 32) * H_ + h;
#pragma unroll
    for (int n = 0; n < N_; ++n) {
        ar[n] = g_CF[(0 * N_ + n) * H_ + h];
        ai[n] = g_CF[(1 * N_ + n) * H_ + h];
        wr[n] = g_CF[(4 * N_ + n) * H_ + h];
        wi[n] = g_CF[(5 * N_ + n) * H_ + h];
        sr[n] = stp[(2 * n + 0) * H_];
        si[n] = stp[(2 * n + 1) * H_];
    }
    int lo = c * CL;
    const float* xp = X + ((size_t)b * L + lo + CL - 1) * H_ + h;
    float* yb = Yb + (size_t)b * Lout * H_ + h;
    for (int p = lo + CL - 1; p >= lo; --p) {
        if (!ds || !(p & 1)) {
            float a0 = 0.0f, a1 = 0.0f;
#pragma unroll
            for (int n = 0; n < N_; ++n) {
                a0 = fmaf(wr[n], sr[n], a0);
                a1 = fmaf(wi[n], si[n], a1);
            }
            yb[(size_t)(ds ? (p >> 1) : p) * H_] = 2.0f * (a0 - a1);
        }
        float u = *xp; xp -= H_;
#pragma unroll
        for (int n = 0; n < N_; ++n) {
            float t = fmaf(ar[n], sr[n], fmaf(-ai[n], si[n], u));
            si[n] = fmaf(ar[n], si[n], ai[n] * sr[n]);
            sr[n] = t;
        }
    }
}

// ---------------------------------------------------------------------------
// Scan pass 2, forward direction: update state with u[l], then
// y = gelu(2*Re(sum_n w0*h) + y_bwd + D*u). Writes COMPACT rows.
// ---------------------------------------------------------------------------
__global__ void scan_fwd(const float* __restrict__ X,
                         const float* __restrict__ Yb,
                         float* __restrict__ Yf,
                         const float* __restrict__ Dv,
                         int L, int CL, int Lout, int ds) {
    int h = blockIdx.x * 256 + threadIdx.x;
    int c = blockIdx.y;
    int b = blockIdx.z;

    float ar[N_], ai[N_], wr[N_], wi[N_], sr[N_], si[N_];
    const float* stp = g_S + (((size_t)(0 * BATCH + b) * NC + c) * 32) * H_ + h;
#pragma unroll
    for (int n = 0; n < N_; ++n) {
        ar[n] = g_CF[(0 * N_ + n) * H_ + h];
        ai[n] = g_CF[(1 * N_ + n) * H_ + h];
        wr[n] = g_CF[(2 * N_ + n) * H_ + h];
        wi[n] = g_CF[(3 * N_ + n) * H_ + h];
        sr[n] = stp[(2 * n + 0) * H_];
        si[n] = stp[(2 * n + 1) * H_];
    }
    float Dh = Dv[h];
    int lo = c * CL;
    const float* xp = X + ((size_t)b * L + lo) * H_ + h;
    const float* yb = Yb + (size_t)b * Lout * H_ + h;
    float* yf = Yf + (size_t)b * Lout * H_ + h;
    for (int l = lo; l < lo + CL; ++l) {
        float u = *xp; xp += H_;
#pragma unroll
        for (int n = 0; n < N_; ++n) {
            float t = fmaf(ar[n], sr[n], fmaf(-ai[n], si[n], u));
            si[n] = fmaf(ar[n], si[n], ai[n] * sr[n]);
            sr[n] = t;
        }
        if (!ds || !(l & 1)) {
            float a0 = 0.0f, a1 = 0.0f;
#pragma unroll
            for (int n = 0; n < N_; ++n) {
                a0 = fmaf(wr[n], sr[n], a0);
                a1 = fmaf(wi[n], si[n], a1);
            }
            size_t pos = (size_t)(ds ? (l >> 1) : l) * H_;
            float yv = 2.0f * (a0 - a1) + yb[pos] + Dh * u;
            yf[pos] = 0.5f * yv * (1.0f + erff(yv * 0.70710678118654752f));
        }
    }
}

// ---------------------------------------------------------------------------
// GLU + residual + LayerNorm. V is COMPACT (M_out rows); residual X is full.
// ---------------------------------------------------------------------------
__global__ void glu_ln_kernel(const float* __restrict__ V,
                              const float* __restrict__ X,
                              const float* __restrict__ nw,
                              const float* __restrict__ nb,
                              float* __restrict__ out, int ds) {
    int row_out = blockIdx.x;
    int row_in  = ds ? row_out * 2 : row_out;
    const float* v = V + (size_t)row_out * (2 * H_);
    const float* x = X + (size_t)row_in * H_;
    int tid = threadIdx.x;

    float vals[3];
    float s = 0.0f, q = 0.0f;
#pragma unroll
    for (int t = 0; t < 3; ++t) {
        int j = tid + t * 256;
        float a = v[j];
        float g = v[j + H_];
        float z = a * (1.0f / (1.0f + expf(-g)));
        float xr = z + x[j];
        vals[t] = xr;
        s += xr;
        q += xr * xr;
    }
    __shared__ float sh[18];
    int lane = tid & 31, wid = tid >> 5;
#pragma unroll
    for (int o = 16; o; o >>= 1) {
        s += __shfl_xor_sync(0xffffffffu, s, o);
        q += __shfl_xor_sync(0xffffffffu, q, o);
    }
    if (lane == 0) { sh[wid] = s; sh[8 + wid] = q; }
    __syncthreads();
    if (tid == 0) {
        float S = 0.0f, Q = 0.0f;
#pragma unroll
        for (int i = 0; i < 8; ++i) { S += sh[i]; Q += sh[8 + i]; }
        float mu = S * (1.0f / H_);
        float var = Q * (1.0f / H_) - mu * mu;
        sh[16] = mu;
        sh[17] = rsqrtf(var + 1e-5f);
    }
    __syncthreads();
    float mu = sh[16], inv = sh[17];
#pragma unroll
    for (int t = 0; t < 3; ++t) {
        int j = tid + t * 256;
        out[(size_t)row_out * H_ + j] = (vals[t] - mu) * inv * nw[j] + nb[j];
    }
}

// ---------------------------------------------------------------------------
// Head
// ---------------------------------------------------------------------------
__global__ void head_kernel(const float* __restrict__ X,
                            const float* __restrict__ W,
                            const float* __restrict__ bb,
                            float* __restrict__ out) {
    int row = blockIdx.x;
    __shared__ float xs[H_];
    for (int j = threadIdx.x; j < H_; j += blockDim.x)
        xs[j] = X[(size_t)row * H_ + j];
    __syncthreads();
    int d = threadIdx.x;
    if (d < NOUTS) {
        float sum = bb[d];
#pragma unroll 4
        for (int k = 0; k < H_; ++k)
            sum = fmaf(xs[k], W[k * NOUTS + d], sum);
        out[(size_t)row * NOUTS + d] = sum;
    }
}

// ---------------------------------------------------------------------------
extern "C" void kernel_launch(void* const* d_in, const int* in_sizes, int n_in,
                              void* d_out, int out_size) {
    const float* x_raw      = (const float*)d_in[1];
    const float* enc_w1     = (const float*)d_in[3];
    const float* enc_b1     = (const float*)d_in[4];
    const float* enc_w2     = (const float*)d_in[5];
    const float* enc_b2     = (const float*)d_in[6];
    const float* log_dt     = (const float*)d_in[7];
    const float* log_A_real = (const float*)d_in[8];
    const float* A_imag     = (const float*)d_in[9];
    const float* C_ri       = (const float*)d_in[10];
    const float* Dv         = (const float*)d_in[11];
    const float* out_w      = (const float*)d_in[12];
    const float* out_b      = (const float*)d_in[13];
    const float* norm_w     = (const float*)d_in[14];
    const float* norm_b     = (const float*)d_in[15];
    const float* wout_w     = (const float*)d_in[16];
    const float* wout_b     = (const float*)d_in[17];

    float *gA, *gB, *gY, *gYT, *gV;
    cudaGetSymbolAddress((void**)&gA,  g_A);
    cudaGetSymbolAddress((void**)&gB,  g_Bf);
    cudaGetSymbolAddress((void**)&gY,  g_Y);
    cudaGetSymbolAddress((void**)&gYT, g_YT);
    cudaGetSymbolAddress((void**)&gV,  g_V);

    // encoder: softsign(x_raw@W1+b1) @ W2 + b2 -> gA (B, L, H)
    enc1_kernel<<<BATCH * LMAX, 256>>>(x_raw, enc_w1, enc_b1, gY);
    sgemm_kernel<false><<<dim3(H_ / 128, (BATCH * LMAX) / 128), 256>>>(
        gY, enc_w2, enc_b2, gA, BATCH * LMAX, H_, H_);

    int Lcur = LMAX;
    float* cur = gA;
    float* nxt = gB;
    for (int i = 0; i < NLAYERS; ++i) {
        int ds   = (i <= 2) ? 1 : 0;
        int Lout = ds ? Lcur / 2 : Lcur;
        int CL   = Lcur / NC;
        int Mout = BATCH * Lout;

        coef_kernel<<<(H_ * N_) / 256, 256>>>(log_dt, log_A_real, A_imag,
                                              C_ri, i, CL);
        scan_pass1<<<dim3(3, NC, BATCH * 2), 256>>>(cur, Lcur, CL);
        scan_fix<<<(2 * BATCH * H_ * N_) / 256, 256>>>();
        scan_bwd<<<dim3(3, NC, BATCH), 256>>>(cur, gYT, Lcur, CL, Lout, ds);
        scan_fwd<<<dim3(3, NC, BATCH), 256>>>(cur, gYT, gY, Dv + i * H_,
                                              Lcur, CL, Lout, ds);
        // V = Ycompact @ out_w^T + out_b  (NT), M = B*Lout rows
        sgemm_kernel<true><<<dim3((2 * H_) / 128, Mout / 128), 256>>>(
            gY, out_w + (size_t)i * 2 * H_ * H_, out_b + (size_t)i * 2 * H_,
            gV, Mout, 2 * H_, H_);
        glu_ln_kernel<<<Mout, 256>>>(gV, cur, norm_w + i * H_, norm_b + i * H_,
                                     nxt, ds);
        Lcur = Lout;
        float* tmp = cur; cur = nxt; nxt = tmp;
    }

    head_kernel<<<BATCH * Lcur, 128>>>(cur, wout_w, wout_b, (float*)d_out);
}

// round 4
// speedup vs baseline: 2.3685x; 1.5777x over previous
#include <cuda_runtime.h>
#include <cuda_bf16.h>
#include <math.h>
#include <stdint.h>

#define H_ 768
#define N_ 16
#define NLAYERS 6
#define NOUTS 38
#define BATCH 8
#define LMAX 2048
#define NC 32
#define K3 2304          // 3 * H_
#define NCH 36           // K3 / 64

#define MAXACT (BATCH*LMAX*H_)

__device__ float g_A [MAXACT];
__device__ float g_Bf[MAXACT];
__device__ float g_YT[MAXACT];
__device__ float g_V [BATCH*LMAX*2*H_];
__device__ float g_S [2*BATCH*NC*2*N_*H_];
__device__ float g_CF[8*N_*H_];
__device__ __nv_bfloat16 g_A3 [(size_t)BATCH*LMAX*K3];   // fat-K activations
__device__ __nv_bfloat16 g_W3 [(size_t)NLAYERS*2*H_*K3]; // fat-K layer weights
__device__ __nv_bfloat16 g_W3e[(size_t)H_*K3];           // fat-K encoder w2^T

// ---------------------------------------------------------------------------
// helpers
// ---------------------------------------------------------------------------
__device__ __forceinline__ uint32_t smem_u32(const void* p) {
    uint32_t a;
    asm("{ .reg .u64 t; cvta.to.shared.u64 t, %1; cvt.u32.u64 %0, t; }"
        : "=r"(a) : "l"(p));
    return a;
}
__device__ __forceinline__ void ldm4(uint32_t* r, uint32_t addr) {
    asm volatile("ldmatrix.sync.aligned.m8n8.x4.shared.b16 {%0,%1,%2,%3}, [%4];"
                 : "=r"(r[0]), "=r"(r[1]), "=r"(r[2]), "=r"(r[3]) : "r"(addr));
}
__device__ __forceinline__ void mma16816(float* c, const uint32_t* a,
                                         const uint32_t* b) {
    asm volatile(
        "mma.sync.aligned.m16n8k16.row.col.f32.bf16.bf16.f32 "
        "{%0,%1,%2,%3}, {%4,%5,%6,%7}, {%8,%9}, {%0,%1,%2,%3};"
        : "+f"(c[0]), "+f"(c[1]), "+f"(c[2]), "+f"(c[3])
        : "r"(a[0]), "r"(a[1]), "r"(a[2]), "r"(a[3]), "r"(b[0]), "r"(b[1]));
}
__device__ __forceinline__ void split_bf16(float x, __nv_bfloat16& hi,
                                           __nv_bfloat16& lo) {
    hi = __float2bfloat16(x);
    lo = __float2bfloat16(x - __bfloat162float(hi));
}

// ---------------------------------------------------------------------------
// HMMA bf16 GEMM: C[M,N] = A3[M,K3] @ B3[N,K3]^T + bias[N]
// grid (N/128, M/128), 256 threads (8 warps of 64x32). K-chunks of 64.
// smem rows are 128B (64 bf16) with SW128 swizzle: unit' = unit ^ (row&7).
// ---------------------------------------------------------------------------
__global__ void __launch_bounds__(256, 1)
hmma_gemm_kernel(const __nv_bfloat16* __restrict__ A3,
                 const __nv_bfloat16* __restrict__ B3,
                 const float* __restrict__ bias,
                 float* __restrict__ C, int Ncols) {
    __shared__ __align__(128) char sA[16384];
    __shared__ __align__(128) char sB[16384];
    const uint32_t sa = smem_u32(sA);
    const uint32_t sb = smem_u32(sB);

    const int tid  = threadIdx.x;
    const int wid  = tid >> 5;
    const int lane = tid & 31;
    const int warp_m = wid >> 2;       // 0..1
    const int warp_n = wid & 3;        // 0..3
    const int m_base = warp_m * 64;
    const int n_base = warp_n * 32;

    const int m0 = blockIdx.y * 128;
    const int n0 = blockIdx.x * 128;
    const __nv_bfloat16* Ab = A3 + (size_t)m0 * K3;
    const __nv_bfloat16* Bb = B3 + (size_t)n0 * K3;

    // staging mapping: thread -> (row = tid>>3 (+32i), seg = tid&7)
    const int st_row = tid >> 3;
    const int st_seg = tid & 7;

    // ldmatrix row/base precompute
    int rA[4], xA[4];
#pragma unroll
    for (int mt = 0; mt < 4; ++mt) {
        rA[mt] = m_base + mt * 16 + (lane & 15);
        xA[mt] = rA[mt] & 7;
    }
    const int uhA = lane >> 4;                       // k half for A
    int rB[2], xB[2];
#pragma unroll
    for (int nt2 = 0; nt2 < 2; ++nt2) {
        rB[nt2] = n_base + nt2 * 16 + ((lane >> 4) << 3) + (lane & 7);
        xB[nt2] = rB[nt2] & 7;
    }
    const int uhB = (lane >> 3) & 1;                 // k half for B

    float acc[4][4][4];
#pragma unroll
    for (int mt = 0; mt < 4; ++mt)
#pragma unroll
        for (int nt = 0; nt < 4; ++nt)
#pragma unroll
            for (int e = 0; e < 4; ++e) acc[mt][nt][e] = 0.0f;

    // load chunk 0 into smem
    {
#pragma unroll
        for (int i = 0; i < 4; ++i) {
            int r = st_row + i * 32;
            uint32_t off = (uint32_t)(r * 128 + ((st_seg ^ (r & 7)) * 16));
            *(float4*)(sA + (off)) = *(const float4*)(Ab + (size_t)r * K3 + st_seg * 8);
            *(float4*)(sB + (off)) = *(const float4*)(Bb + (size_t)r * K3 + st_seg * 8);
        }
    }
    __syncthreads();

    for (int c = 0; c < NCH; ++c) {
        float4 pa[4], pb[4];
        if (c + 1 < NCH) {
#pragma unroll
            for (int i = 0; i < 4; ++i) {
                int r = st_row + i * 32;
                pa[i] = *(const float4*)(Ab + (size_t)r * K3 + (c + 1) * 64 + st_seg * 8);
                pb[i] = *(const float4*)(Bb + (size_t)r * K3 + (c + 1) * 64 + st_seg * 8);
            }
        }
#pragma unroll
        for (int kk = 0; kk < 4; ++kk) {
            uint32_t af[4][4], bf[2][4];
#pragma unroll
            for (int mt = 0; mt < 4; ++mt) {
                uint32_t addr = sa + (uint32_t)(rA[mt] * 128 +
                                (((kk * 2 + uhA) ^ xA[mt]) * 16));
                ldm4(af[mt], addr);
            }
#pragma unroll
            for (int nt2 = 0; nt2 < 2; ++nt2) {
                uint32_t addr = sb + (uint32_t)(rB[nt2] * 128 +
                                (((kk * 2 + uhB) ^ xB[nt2]) * 16));
                ldm4(bf[nt2], addr);
            }
#pragma unroll
            for (int mt = 0; mt < 4; ++mt)
#pragma unroll
                for (int nt = 0; nt < 4; ++nt)
                    mma16816(acc[mt][nt], af[mt], &bf[nt >> 1][(nt & 1) * 2]);
        }
        __syncthreads();
        if (c + 1 < NCH) {
#pragma unroll
            for (int i = 0; i < 4; ++i) {
                int r = st_row + i * 32;
                uint32_t off = (uint32_t)(r * 128 + ((st_seg ^ (r & 7)) * 16));
                *(float4*)(sA + off) = pa[i];
                *(float4*)(sB + off) = pb[i];
            }
            __syncthreads();
        }
    }

    // epilogue: c0=C[gr][gc], c1=C[gr][gc+1], c2=C[gr+8][gc], c3=C[gr+8][gc+1]
    const int gr = lane >> 2;
    const int gc = (lane & 3) * 2;
#pragma unroll
    for (int nt = 0; nt < 4; ++nt) {
        int ncol = n0 + n_base + nt * 8 + gc;
        float b0 = bias[ncol], b1 = bias[ncol + 1];
#pragma unroll
        for (int mt = 0; mt < 4; ++mt) {
            int mr = m0 + m_base + mt * 16 + gr;
            float2 v0 = make_float2(acc[mt][nt][0] + b0, acc[mt][nt][1] + b1);
            float2 v1 = make_float2(acc[mt][nt][2] + b0, acc[mt][nt][3] + b1);
            *(float2*)&C[(size_t)mr * Ncols + ncol] = v0;
            *(float2*)&C[(size_t)(mr + 8) * Ncols + ncol] = v1;
        }
    }
}

// ---------------------------------------------------------------------------
// Weight converters (fat-K layout: A3=[hi|lo|hi], B3=[hi|hi|lo])
// ---------------------------------------------------------------------------
__global__ void wconv_layers(const float* __restrict__ out_w) {
    size_t idx = (size_t)blockIdx.x * blockDim.x + threadIdx.x;
    int k = idx % H_;
    size_t nr = idx / H_;            // layer*1536 + n
    float w = out_w[idx];
    __nv_bfloat16 hi, lo; split_bf16(w, hi, lo);
    __nv_bfloat16* dst = g_W3 + nr * K3;
    dst[k] = hi; dst[H_ + k] = hi; dst[2 * H_ + k] = lo;
}

__global__ void wconv_enc(const float* __restrict__ w2) {
    __shared__ float t[32][33];
    int k0 = blockIdx.y * 32, n0 = blockIdx.x * 32;
    int tx = threadIdx.x;
#pragma unroll
    for (int i = threadIdx.y; i < 32; i += 8)
        t[i][tx] = w2[(size_t)(k0 + i) * H_ + n0 + tx];
    __syncthreads();
#pragma unroll
    for (int i = threadIdx.y; i < 32; i += 8) {
        float w = t[tx][i];
        __nv_bfloat16 hi, lo; split_bf16(w, hi, lo);
        __nv_bfloat16* dst = g_W3e + (size_t)(n0 + i) * K3;
        dst[k0 + tx] = hi; dst[H_ + k0 + tx] = hi; dst[2 * H_ + k0 + tx] = lo;
    }
}

// ---------------------------------------------------------------------------
// Encoder stage 1 -> fat-K split activations
// ---------------------------------------------------------------------------
__global__ void enc1_kernel(const float* __restrict__ xr,
                            const float* __restrict__ w1,
                            const float* __restrict__ b1) {
    int row = blockIdx.x;
    __shared__ float xs[8];
    if (threadIdx.x < 8) xs[threadIdx.x] = xr[(size_t)row * 8 + threadIdx.x];
    __syncthreads();
    __nv_bfloat16* dst = g_A3 + (size_t)row * K3;
    for (int j = threadIdx.x; j < H_; j += blockDim.x) {
        float s = b1[j];
#pragma unroll
        for (int k = 0; k < 8; ++k) s = fmaf(xs[k], w1[k * H_ + j], s);
        float v = s / (1.0f + fabsf(s));
        __nv_bfloat16 hi, lo; split_bf16(v, hi, lo);
        dst[j] = hi; dst[H_ + j] = lo; dst[2 * H_ + j] = hi;
    }
}

// ---------------------------------------------------------------------------
// SSM coefficients
// ---------------------------------------------------------------------------
__global__ void coef_kernel(const float* __restrict__ log_dt,
                            const float* __restrict__ log_A_real,
                            const float* __restrict__ A_imag,
                            const float* __restrict__ C_ri,
                            int layer, int CL) {
    int idx = blockIdx.x * blockDim.x + threadIdx.x;
    int h = idx % H_;
    int n = idx / H_;

    float dt  = expf(log_dt[layer * H_ + h]);
    int pidx  = (layer * H_ + h) * N_ + n;
    float Are = -expf(log_A_real[pidx]);
    float Aim = A_imag[pidx];
    float dr = dt * Are, di = dt * Aim;
    float e  = expf(dr);
    float ar = e * cosf(di);
    float ai = e * sinf(di);
    float invA2 = 1.0f / (Are * Are + Aim * Aim);
    float dBr = ((ar - 1.0f) * Are + ai * Aim) * invA2;
    float dBi = (ai * Are - (ar - 1.0f) * Aim) * invA2;

    size_t c0idx = ((((size_t)layer * 2 + 0) * H_ + h) * N_ + n) * 2;
    size_t c1idx = ((((size_t)layer * 2 + 1) * H_ + h) * N_ + n) * 2;
    float c0r = C_ri[c0idx], c0i = C_ri[c0idx + 1];
    float c1r = C_ri[c1idx], c1i = C_ri[c1idx + 1];

    float eL = expf(CL * dr);
    g_CF[(0 * N_ + n) * H_ + h] = ar;
    g_CF[(1 * N_ + n) * H_ + h] = ai;
    g_CF[(2 * N_ + n) * H_ + h] = c0r * dBr - c0i * dBi;
    g_CF[(3 * N_ + n) * H_ + h] = c0r * dBi + c0i * dBr;
    g_CF[(4 * N_ + n) * H_ + h] = c1r * dBr - c1i * dBi;
    g_CF[(5 * N_ + n) * H_ + h] = c1r * dBi + c1i * dBr;
    g_CF[(6 * N_ + n) * H_ + h] = eL * cosf(CL * di);
    g_CF[(7 * N_ + n) * H_ + h] = eL * sinf(CL * di);
}

// ---------------------------------------------------------------------------
// Scan pass 1: per-chunk local final states (zero init), both directions.
// ---------------------------------------------------------------------------
__global__ void scan_pass1(const float* __restrict__ X, int L, int CL) {
    int h   = blockIdx.x * 256 + threadIdx.x;
    int c   = blockIdx.y;
    int bz  = blockIdx.z;
    int b   = bz >> 1;
    int dir = bz & 1;

    float ar[N_], ai[N_], sr[N_], si[N_];
#pragma unroll
    for (int n = 0; n < N_; ++n) {
        ar[n] = g_CF[(0 * N_ + n) * H_ + h];
        ai[n] = g_CF[(1 * N_ + n) * H_ + h];
        sr[n] = 0.0f; si[n] = 0.0f;
    }
    int lo = c * CL;
    const float* xp = (dir == 0) ? X + ((size_t)b * L + lo) * H_ + h
                                 : X + ((size_t)b * L + lo + CL - 1) * H_ + h;
    int step = (dir == 0) ? H_ : -H_;
    for (int l = 0; l < CL; ++l) {
        float u = *xp; xp += step;
#pragma unroll
        for (int n = 0; n < N_; ++n) {
            float t = fmaf(ar[n], sr[n], fmaf(-ai[n], si[n], u));
            si[n] = fmaf(ar[n], si[n], ai[n] * sr[n]);
            sr[n] = t;
        }
    }
    float* f = g_S + (((size_t)(dir * BATCH + b) * NC + c) * 32) * H_ + h;
#pragma unroll
    for (int n = 0; n < N_; ++n) {
        f[(2 * n + 0) * H_] = sr[n];
        f[(2 * n + 1) * H_] = si[n];
    }
}

__global__ void scan_fix() {
    int idx = blockIdx.x * blockDim.x + threadIdx.x;
    int h   = idx % H_;
    int n   = (idx / H_) % N_;
    int b   = (idx / (H_ * N_)) % BATCH;
    int dir = idx / (H_ * N_ * BATCH);

    float aLr = g_CF[(6 * N_ + n) * H_ + h];
    float aLi = g_CF[(7 * N_ + n) * H_ + h];

    float accr = 0.0f, acci = 0.0f;
    for (int c = 0; c < NC; ++c) {
        int cc = (dir == 0) ? c : (NC - 1 - c);
        float* p = g_S + (((size_t)(dir * BATCH + b) * NC + cc) * 32) * H_ + h;
        float fr = p[(2 * n + 0) * H_];
        float fi = p[(2 * n + 1) * H_];
        p[(2 * n + 0) * H_] = accr;
        p[(2 * n + 1) * H_] = acci;
        float t = aLr * accr - aLi * acci + fr;
        acci = aLr * acci + aLi * accr + fi;
        accr = t;
    }
}

__global__ void scan_bwd(const float* __restrict__ X, float* __restrict__ Yb,
                         int L, int CL, int Lout, int ds) {
    int h = blockIdx.x * 256 + threadIdx.x;
    int c = blockIdx.y;
    int b = blockIdx.z;

    float ar[N_], ai[N_], wr[N_], wi[N_], sr[N_], si[N_];
    const float* stp = g_S + (((size_t)(1 * BATCH + b) * NC + c) * 32) * H_ + h;
#pragma unroll
    for (int n = 0; n < N_; ++n) {
        ar[n] = g_CF[(0 * N_ + n) * H_ + h];
        ai[n] = g_CF[(1 * N_ + n) * H_ + h];
        wr[n] = g_CF[(4 * N_ + n) * H_ + h];
        wi[n] = g_CF[(5 * N_ + n) * H_ + h];
        sr[n] = stp[(2 * n + 0) * H_];
        si[n] = stp[(2 * n + 1) * H_];
    }
    int lo = c * CL;
    const float* xp = X + ((size_t)b * L + lo + CL - 1) * H_ + h;
    float* yb = Yb + (size_t)b * Lout * H_ + h;
    for (int p = lo + CL - 1; p >= lo; --p) {
        if (!ds || !(p & 1)) {
            float a0 = 0.0f, a1 = 0.0f;
#pragma unroll
            for (int n = 0; n < N_; ++n) {
                a0 = fmaf(wr[n], sr[n], a0);
                a1 = fmaf(wi[n], si[n], a1);
            }
            yb[(size_t)(ds ? (p >> 1) : p) * H_] = 2.0f * (a0 - a1);
        }
        float u = *xp; xp -= H_;
#pragma unroll
        for (int n = 0; n < N_; ++n) {
            float t = fmaf(ar[n], sr[n], fmaf(-ai[n], si[n], u));
            si[n] = fmaf(ar[n], si[n], ai[n] * sr[n]);
            sr[n] = t;
        }
    }
}

// Forward pass: writes gelu result into fat-K split g_A3 (compact rows).
__global__ void scan_fwd(const float* __restrict__ X,
                         const float* __restrict__ Yb,
                         const float* __restrict__ Dv,
                         int L, int CL, int Lout, int ds) {
    int h = blockIdx.x * 256 + threadIdx.x;
    int c = blockIdx.y;
    int b = blockIdx.z;

    float ar[N_], ai[N_], wr[N_], wi[N_], sr[N_], si[N_];
    const float* stp = g_S + (((size_t)(0 * BATCH + b) * NC + c) * 32) * H_ + h;
#pragma unroll
    for (int n = 0; n < N_; ++n) {
        ar[n] = g_CF[(0 * N_ + n) * H_ + h];
        ai[n] = g_CF[(1 * N_ + n) * H_ + h];
        wr[n] = g_CF[(2 * N_ + n) * H_ + h];
        wi[n] = g_CF[(3 * N_ + n) * H_ + h];
        sr[n] = stp[(2 * n + 0) * H_];
        si[n] = stp[(2 * n + 1) * H_];
    }
    float Dh = Dv[h];
    int lo = c * CL;
    const float* xp = X + ((size_t)b * L + lo) * H_ + h;
    const float* yb = Yb + (size_t)b * Lout * H_ + h;
    for (int l = lo; l < lo + CL; ++l) {
        float u = *xp; xp += H_;
#pragma unroll
        for (int n = 0; n < N_; ++n) {
            float t = fmaf(ar[n], sr[n], fmaf(-ai[n], si[n], u));
            si[n] = fmaf(ar[n], si[n], ai[n] * sr[n]);
            sr[n] = t;
        }
        if (!ds || !(l & 1)) {
            float a0 = 0.0f, a1 = 0.0f;
#pragma unroll
            for (int n = 0; n < N_; ++n) {
                a0 = fmaf(wr[n], sr[n], a0);
                a1 = fmaf(wi[n], si[n], a1);
            }
            int lrow = ds ? (l >> 1) : l;
            size_t rr = (size_t)b * Lout + lrow;
            float yv = 2.0f * (a0 - a1) + yb[(size_t)lrow * H_] + Dh * u;
            yv = 0.5f * yv * (1.0f + erff(yv * 0.70710678118654752f));
            __nv_bfloat16 hi, lo2; split_bf16(yv, hi, lo2);
            __nv_bfloat16* dst = g_A3 + rr * K3;
            dst[h] = hi; dst[H_ + h] = lo2; dst[2 * H_ + h] = hi;
        }
    }
}

// ---------------------------------------------------------------------------
// GLU + residual + LayerNorm
// ---------------------------------------------------------------------------
__global__ void glu_ln_kernel(const float* __restrict__ V,
                              const float* __restrict__ X,
                              const float* __restrict__ nw,
                              const float* __restrict__ nb,
                              float* __restrict__ out, int ds) {
    int row_out = blockIdx.x;
    int row_in  = ds ? row_out * 2 : row_out;
    const float* v = V + (size_t)row_out * (2 * H_);
    const float* x = X + (size_t)row_in * H_;
    int tid = threadIdx.x;

    float vals[3];
    float s = 0.0f, q = 0.0f;
#pragma unroll
    for (int t = 0; t < 3; ++t) {
        int j = tid + t * 256;
        float a = v[j];
        float g = v[j + H_];
        float z = a * (1.0f / (1.0f + expf(-g)));
        float xr = z + x[j];
        vals[t] = xr;
        s += xr;
        q += xr * xr;
    }
    __shared__ float sh[18];
    int lane = tid & 31, wid = tid >> 5;
#pragma unroll
    for (int o = 16; o; o >>= 1) {
        s += __shfl_xor_sync(0xffffffffu, s, o);
        q += __shfl_xor_sync(0xffffffffu, q, o);
    }
    if (lane == 0) { sh[wid] = s; sh[8 + wid] = q; }
    __syncthreads();
    if (tid == 0) {
        float S = 0.0f, Q = 0.0f;
#pragma unroll
        for (int i = 0; i < 8; ++i) { S += sh[i]; Q += sh[8 + i]; }
        float mu = S * (1.0f / H_);
        float var = Q * (1.0f / H_) - mu * mu;
        sh[16] = mu;
        sh[17] = rsqrtf(var + 1e-5f);
    }
    __syncthreads();
    float mu = sh[16], inv = sh[17];
#pragma unroll
    for (int t = 0; t < 3; ++t) {
        int j = tid + t * 256;
        out[(size_t)row_out * H_ + j] = (vals[t] - mu) * inv * nw[j] + nb[j];
    }
}

// ---------------------------------------------------------------------------
// Head
// ---------------------------------------------------------------------------
__global__ void head_kernel(const float* __restrict__ X,
                            const float* __restrict__ W,
                            const float* __restrict__ bb,
                            float* __restrict__ out) {
    int row = blockIdx.x;
    __shared__ float xs[H_];
    for (int j = threadIdx.x; j < H_; j += blockDim.x)
        xs[j] = X[(size_t)row * H_ + j];
    __syncthreads();
    int d = threadIdx.x;
    if (d < NOUTS) {
        float sum = bb[d];
#pragma unroll 4
        for (int k = 0; k < H_; ++k)
            sum = fmaf(xs[k], W[k * NOUTS + d], sum);
        out[(size_t)row * NOUTS + d] = sum;
    }
}

// ---------------------------------------------------------------------------
extern "C" void kernel_launch(void* const* d_in, const int* in_sizes, int n_in,
                              void* d_out, int out_size) {
    const float* x_raw      = (const float*)d_in[1];
    const float* enc_w1     = (const float*)d_in[3];
    const float* enc_b1     = (const float*)d_in[4];
    const float* enc_w2     = (const float*)d_in[5];
    const float* enc_b2     = (const float*)d_in[6];
    const float* log_dt     = (const float*)d_in[7];
    const float* log_A_real = (const float*)d_in[8];
    const float* A_imag     = (const float*)d_in[9];
    const float* C_ri       = (const float*)d_in[10];
    const float* Dv         = (const float*)d_in[11];
    const float* out_w      = (const float*)d_in[12];
    const float* out_b      = (const float*)d_in[13];
    const float* norm_w     = (const float*)d_in[14];
    const float* norm_b     = (const float*)d_in[15];
    const float* wout_w     = (const float*)d_in[16];
    const float* wout_b     = (const float*)d_in[17];

    float *gA, *gB, *gYT, *gV;
    cudaGetSymbolAddress((void**)&gA,  g_A);
    cudaGetSymbolAddress((void**)&gB,  g_Bf);
    cudaGetSymbolAddress((void**)&gYT, g_YT);
    cudaGetSymbolAddress((void**)&gV,  g_V);
    __nv_bfloat16 *gA3, *gW3, *gW3e;
    cudaGetSymbolAddress((void**)&gA3,  g_A3);
    cudaGetSymbolAddress((void**)&gW3,  g_W3);
    cudaGetSymbolAddress((void**)&gW3e, g_W3e);

    // weight conversions (fat-K bf16 split)
    wconv_layers<<<(NLAYERS * 2 * H_ * H_) / 256, 256>>>(out_w);
    wconv_enc<<<dim3(H_ / 32, H_ / 32), dim3(32, 8)>>>(enc_w2);

    // encoder
    enc1_kernel<<<BATCH * LMAX, 256>>>(x_raw, enc_w1, enc_b1);
    hmma_gemm_kernel<<<dim3(H_ / 128, (BATCH * LMAX) / 128), 256>>>(
        gA3, gW3e, enc_b2, gA, H_);

    int Lcur = LMAX;
    float* cur = gA;
    float* nxt = gB;
    for (int i = 0; i < NLAYERS; ++i) {
        int ds   = (i <= 2) ? 1 : 0;
        int Lout = ds ? Lcur / 2 : Lcur;
        int CL   = Lcur / NC;
        int Mout = BATCH * Lout;

        coef_kernel<<<(H_ * N_) / 256, 256>>>(log_dt, log_A_real, A_imag,
                                              C_ri, i, CL);
        scan_pass1<<<dim3(3, NC, BATCH * 2), 256>>>(cur, Lcur, CL);
        scan_fix<<<(2 * BATCH * H_ * N_) / 256, 256>>>();
        scan_bwd<<<dim3(3, NC, BATCH), 256>>>(cur, gYT, Lcur, CL, Lout, ds);
        scan_fwd<<<dim3(3, NC, BATCH), 256>>>(cur, gYT, Dv + i * H_,
                                              Lcur, CL, Lout, ds);
        hmma_gemm_kernel<<<dim3((2 * H_) / 128, Mout / 128), 256>>>(
            gA3, gW3 + (size_t)i * 2 * H_ * K3, out_b + (size_t)i * 2 * H_,
            gV, 2 * H_);
        glu_ln_kernel<<<Mout, 256>>>(gV, cur, norm_w + i * H_, norm_b + i * H_,
                                     nxt, ds);
        Lcur = Lout;
        float* tmp = cur; cur = nxt; nxt = tmp;
    }

    head_kernel<<<BATCH * Lcur, 128>>>(cur, wout_w, wout_b, (float*)d_out);
}

// round 5
// speedup vs baseline: 2.5300x; 1.0682x over previous
#include <cuda_runtime.h>
#include <cuda_bf16.h>
#include <math.h>
#include <stdint.h>

#define H_ 768
#define N_ 16
#define NLAYERS 6
#define NOUTS 38
#define BATCH 8
#define LMAX 2048
#define NCMAX 64         // max chunks per sequence (CL fixed at 32)
#define CL_ 32
#define K3 2304          // 3 * H_
#define NCH 36           // K3 / 64
#define NSTAGE 3
#define STAGE_BYTES 32768
#define GSMEM (NSTAGE * STAGE_BYTES)

#define MAXACT (BATCH*LMAX*H_)

__device__ float g_A [MAXACT];
__device__ float g_Bf[MAXACT];
__device__ float g_V [BATCH*LMAX*2*H_];
__device__ float g_S [(size_t)2*BATCH*NCMAX*2*N_*H_];
__device__ float g_CF[8*N_*H_];
__device__ __nv_bfloat16 g_A3 [(size_t)BATCH*LMAX*K3];   // fat-K activations
__device__ __nv_bfloat16 g_W3 [(size_t)NLAYERS*2*H_*K3]; // fat-K layer weights
__device__ __nv_bfloat16 g_W3e[(size_t)H_*K3];           // fat-K encoder w2^T

// ---------------------------------------------------------------------------
// helpers
// ---------------------------------------------------------------------------
__device__ __forceinline__ uint32_t smem_u32(const void* p) {
    uint32_t a;
    asm("{ .reg .u64 t; cvta.to.shared.u64 t, %1; cvt.u32.u64 %0, t; }"
        : "=r"(a) : "l"(p));
    return a;
}
__device__ __forceinline__ void ldm4(uint32_t* r, uint32_t addr) {
    asm volatile("ldmatrix.sync.aligned.m8n8.x4.shared.b16 {%0,%1,%2,%3}, [%4];"
                 : "=r"(r[0]), "=r"(r[1]), "=r"(r[2]), "=r"(r[3]) : "r"(addr));
}
__device__ __forceinline__ void mma16816(float* c, const uint32_t* a,
                                         const uint32_t* b) {
    asm volatile(
        "mma.sync.aligned.m16n8k16.row.col.f32.bf16.bf16.f32 "
        "{%0,%1,%2,%3}, {%4,%5,%6,%7}, {%8,%9}, {%0,%1,%2,%3};"
        : "+f"(c[0]), "+f"(c[1]), "+f"(c[2]), "+f"(c[3])
        : "r"(a[0]), "r"(a[1]), "r"(a[2]), "r"(a[3]), "r"(b[0]), "r"(b[1]));
}
__device__ __forceinline__ void cp16(uint32_t saddr, const void* g) {
    asm volatile("cp.async.cg.shared.global [%0], [%1], 16;"
                 :: "r"(saddr), "l"(g));
}
__device__ __forceinline__ void cp_commit() {
    asm volatile("cp.async.commit_group;" ::: "memory");
}
template <int Nw>
__device__ __forceinline__ void cp_wait() {
    asm volatile("cp.async.wait_group %0;" :: "n"(Nw) : "memory");
}
__device__ __forceinline__ void split_bf16(float x, __nv_bfloat16& hi,
                                           __nv_bfloat16& lo) {
    hi = __float2bfloat16(x);
    lo = __float2bfloat16(x - __bfloat162float(hi));
}

// ---------------------------------------------------------------------------
// HMMA bf16 GEMM, cp.async 3-stage pipeline.
// C[M,N] = A3[M,K3] @ B3[N,K3]^T + bias[N]
// grid (N/128, M/128), 256 threads (8 warps of 64x32). K-chunks of 64.
// ---------------------------------------------------------------------------
__global__ void __launch_bounds__(256, 2)
hmma_gemm_kernel(const __nv_bfloat16* __restrict__ A3,
                 const __nv_bfloat16* __restrict__ B3,
                 const float* __restrict__ bias,
                 float* __restrict__ C, int Ncols) {
    extern __shared__ __align__(128) char smem[];
    const uint32_t sbase = smem_u32(smem);

    const int tid  = threadIdx.x;
    const int wid  = tid >> 5;
    const int lane = tid & 31;
    const int warp_m = wid >> 2;
    const int warp_n = wid & 3;
    const int m_base = warp_m * 64;
    const int n_base = warp_n * 32;

    const int m0 = blockIdx.y * 128;
    const int n0 = blockIdx.x * 128;
    const __nv_bfloat16* Ab = A3 + (size_t)m0 * K3;
    const __nv_bfloat16* Bb = B3 + (size_t)n0 * K3;

    const int st_row = tid >> 3;
    const int st_seg = tid & 7;
    // per-thread swizzled smem offsets for the 4 staged rows (same for A/B)
    uint32_t st_off[4];
#pragma unroll
    for (int i = 0; i < 4; ++i) {
        int r = st_row + i * 32;
        st_off[i] = (uint32_t)(r * 128 + ((st_seg ^ (r & 7)) * 16));
    }

    // ldmatrix row/base precompute
    int rA[4], xA[4];
#pragma unroll
    for (int mt = 0; mt < 4; ++mt) {
        rA[mt] = m_base + mt * 16 + (lane & 15);
        xA[mt] = rA[mt] & 7;
    }
    const int uhA = lane >> 4;
    int rB[2], xB[2];
#pragma unroll
    for (int nt2 = 0; nt2 < 2; ++nt2) {
        rB[nt2] = n_base + nt2 * 16 + ((lane >> 4) << 3) + (lane & 7);
        xB[nt2] = rB[nt2] & 7;
    }
    const int uhB = (lane >> 3) & 1;

    float acc[4][4][4];
#pragma unroll
    for (int mt = 0; mt < 4; ++mt)
#pragma unroll
        for (int nt = 0; nt < 4; ++nt)
#pragma unroll
            for (int e = 0; e < 4; ++e) acc[mt][nt][e] = 0.0f;

    // prologue: issue stages 0..2
#pragma unroll
    for (int s = 0; s < NSTAGE; ++s) {
        uint32_t sa = sbase + s * STAGE_BYTES;
        uint32_t sb = sa + 16384;
#pragma unroll
        for (int i = 0; i < 4; ++i) {
            int r = st_row + i * 32;
            cp16(sa + st_off[i], Ab + (size_t)r * K3 + s * 64 + st_seg * 8);
            cp16(sb + st_off[i], Bb + (size_t)r * K3 + s * 64 + st_seg * 8);
        }
        cp_commit();
    }

    for (int c = 0; c < NCH; ++c) {
        cp_wait<NSTAGE - 1>();
        __syncthreads();
        int buf = c % NSTAGE;
        uint32_t sa = sbase + buf * STAGE_BYTES;
        uint32_t sb = sa + 16384;
#pragma unroll
        for (int kk = 0; kk < 4; ++kk) {
            uint32_t af[4][4], bf[2][4];
#pragma unroll
            for (int mt = 0; mt < 4; ++mt)
                ldm4(af[mt], sa + (uint32_t)(rA[mt] * 128 +
                             (((kk * 2 + uhA) ^ xA[mt]) * 16)));
#pragma unroll
            for (int nt2 = 0; nt2 < 2; ++nt2)
                ldm4(bf[nt2], sb + (uint32_t)(rB[nt2] * 128 +
                              (((kk * 2 + uhB) ^ xB[nt2]) * 16)));
#pragma unroll
            for (int mt = 0; mt < 4; ++mt)
#pragma unroll
                for (int nt = 0; nt < 4; ++nt)
                    mma16816(acc[mt][nt], af[mt], &bf[nt >> 1][(nt & 1) * 2]);
        }
        __syncthreads();
        if (c + NSTAGE < NCH) {
#pragma unroll
            for (int i = 0; i < 4; ++i) {
                int r = st_row + i * 32;
                cp16(sa + st_off[i],
                     Ab + (size_t)r * K3 + (c + NSTAGE) * 64 + st_seg * 8);
                cp16(sb + st_off[i],
                     Bb + (size_t)r * K3 + (c + NSTAGE) * 64 + st_seg * 8);
            }
        }
        cp_commit();   // commit every iter (possibly empty) to keep counts aligned
    }

    // epilogue
    const int gr = lane >> 2;
    const int gc = (lane & 3) * 2;
#pragma unroll
    for (int nt = 0; nt < 4; ++nt) {
        int ncol = n0 + n_base + nt * 8 + gc;
        float b0 = bias[ncol], b1 = bias[ncol + 1];
#pragma unroll
        for (int mt = 0; mt < 4; ++mt) {
            int mr = m0 + m_base + mt * 16 + gr;
            float2 v0 = make_float2(acc[mt][nt][0] + b0, acc[mt][nt][1] + b1);
            float2 v1 = make_float2(acc[mt][nt][2] + b0, acc[mt][nt][3] + b1);
            *(float2*)&C[(size_t)mr * Ncols + ncol] = v0;
            *(float2*)&C[(size_t)(mr + 8) * Ncols + ncol] = v1;
        }
    }
}

// ---------------------------------------------------------------------------
// Weight converters (fat-K layout: A3=[hi|lo|hi], B3=[hi|hi|lo])
// ---------------------------------------------------------------------------
__global__ void wconv_layers(const float* __restrict__ out_w) {
    size_t idx = (size_t)blockIdx.x * blockDim.x + threadIdx.x;
    int k = idx % H_;
    size_t nr = idx / H_;
    float w = out_w[idx];
    __nv_bfloat16 hi, lo; split_bf16(w, hi, lo);
    __nv_bfloat16* dst = g_W3 + nr * K3;
    dst[k] = hi; dst[H_ + k] = hi; dst[2 * H_ + k] = lo;
}

__global__ void wconv_enc(const float* __restrict__ w2) {
    __shared__ float t[32][33];
    int k0 = blockIdx.y * 32, n0 = blockIdx.x * 32;
    int tx = threadIdx.x;
#pragma unroll
    for (int i = threadIdx.y; i < 32; i += 8)
        t[i][tx] = w2[(size_t)(k0 + i) * H_ + n0 + tx];
    __syncthreads();
#pragma unroll
    for (int i = threadIdx.y; i < 32; i += 8) {
        float w = t[tx][i];
        __nv_bfloat16 hi, lo; split_bf16(w, hi, lo);
        __nv_bfloat16* dst = g_W3e + (size_t)(n0 + i) * K3;
        dst[k0 + tx] = hi; dst[H_ + k0 + tx] = hi; dst[2 * H_ + k0 + tx] = lo;
    }
}

// ---------------------------------------------------------------------------
// Encoder stage 1 -> fat-K split activations
// ---------------------------------------------------------------------------
__global__ void enc1_kernel(const float* __restrict__ xr,
                            const float* __restrict__ w1,
                            const float* __restrict__ b1) {
    int row = blockIdx.x;
    __shared__ float xs[8];
    if (threadIdx.x < 8) xs[threadIdx.x] = xr[(size_t)row * 8 + threadIdx.x];
    __syncthreads();
    __nv_bfloat16* dst = g_A3 + (size_t)row * K3;
    for (int j = threadIdx.x; j < H_; j += blockDim.x) {
        float s = b1[j];
#pragma unroll
        for (int k = 0; k < 8; ++k) s = fmaf(xs[k], w1[k * H_ + j], s);
        float v = s / (1.0f + fabsf(s));
        __nv_bfloat16 hi, lo; split_bf16(v, hi, lo);
        dst[j] = hi; dst[H_ + j] = lo; dst[2 * H_ + j] = hi;
    }
}

// ---------------------------------------------------------------------------
// SSM coefficients (CL = 32 fixed)
// ---------------------------------------------------------------------------
__global__ void coef_kernel(const float* __restrict__ log_dt,
                            const float* __restrict__ log_A_real,
                            const float* __restrict__ A_imag,
                            const float* __restrict__ C_ri,
                            int layer) {
    int idx = blockIdx.x * blockDim.x + threadIdx.x;
    int h = idx % H_;
    int n = idx / H_;

    float dt  = expf(log_dt[layer * H_ + h]);
    int pidx  = (layer * H_ + h) * N_ + n;
    float Are = -expf(log_A_real[pidx]);
    float Aim = A_imag[pidx];
    float dr = dt * Are, di = dt * Aim;
    float e  = expf(dr);
    float ar = e * cosf(di);
    float ai = e * sinf(di);
    float invA2 = 1.0f / (Are * Are + Aim * Aim);
    float dBr = ((ar - 1.0f) * Are + ai * Aim) * invA2;
    float dBi = (ai * Are - (ar - 1.0f) * Aim) * invA2;

    size_t c0idx = ((((size_t)layer * 2 + 0) * H_ + h) * N_ + n) * 2;
    size_t c1idx = ((((size_t)layer * 2 + 1) * H_ + h) * N_ + n) * 2;
    float c0r = C_ri[c0idx], c0i = C_ri[c0idx + 1];
    float c1r = C_ri[c1idx], c1i = C_ri[c1idx + 1];

    float eL = expf(CL_ * dr);
    g_CF[(0 * N_ + n) * H_ + h] = ar;
    g_CF[(1 * N_ + n) * H_ + h] = ai;
    g_CF[(2 * N_ + n) * H_ + h] = c0r * dBr - c0i * dBi;
    g_CF[(3 * N_ + n) * H_ + h] = c0r * dBi + c0i * dBr;
    g_CF[(4 * N_ + n) * H_ + h] = c1r * dBr - c1i * dBi;
    g_CF[(5 * N_ + n) * H_ + h] = c1r * dBi + c1i * dBr;
    g_CF[(6 * N_ + n) * H_ + h] = eL * cosf(CL_ * di);
    g_CF[(7 * N_ + n) * H_ + h] = eL * sinf(CL_ * di);
}

// ---------------------------------------------------------------------------
// Scan pass 1: per-chunk (CL=32) local final states, both directions.
// grid (3, NCv, B*2), block 256.
// ---------------------------------------------------------------------------
__global__ void scan_pass1(const float* __restrict__ X, int L) {
    int h   = blockIdx.x * 256 + threadIdx.x;
    int c   = blockIdx.y;
    int NCv = gridDim.y;
    int bz  = blockIdx.z;
    int b   = bz >> 1;
    int dir = bz & 1;

    float ar[N_], ai[N_], sr[N_], si[N_];
#pragma unroll
    for (int n = 0; n < N_; ++n) {
        ar[n] = g_CF[(0 * N_ + n) * H_ + h];
        ai[n] = g_CF[(1 * N_ + n) * H_ + h];
        sr[n] = 0.0f; si[n] = 0.0f;
    }
    int lo = c * CL_;
    const float* xp = (dir == 0) ? X + ((size_t)b * L + lo) * H_ + h
                                 : X + ((size_t)b * L + lo + CL_ - 1) * H_ + h;
    int step = (dir == 0) ? H_ : -H_;
#pragma unroll 4
    for (int l = 0; l < CL_; ++l) {
        float u = *xp; xp += step;
#pragma unroll
        for (int n = 0; n < N_; ++n) {
            float t = fmaf(ar[n], sr[n], fmaf(-ai[n], si[n], u));
            si[n] = fmaf(ar[n], si[n], ai[n] * sr[n]);
            sr[n] = t;
        }
    }
    float* f = g_S + (((size_t)(dir * BATCH + b) * NCv + c) * 32) * H_ + h;
#pragma unroll
    for (int n = 0; n < N_; ++n) {
        f[(2 * n + 0) * H_] = sr[n];
        f[(2 * n + 1) * H_] = si[n];
    }
}

// ---------------------------------------------------------------------------
// Scan fix: serial chunk-state composition; finals -> init states.
// ---------------------------------------------------------------------------
__global__ void scan_fix(int NCv) {
    int idx = blockIdx.x * blockDim.x + threadIdx.x;
    int h   = idx % H_;
    int n   = (idx / H_) % N_;
    int b   = (idx / (H_ * N_)) % BATCH;
    int dir = idx / (H_ * N_ * BATCH);

    float aLr = g_CF[(6 * N_ + n) * H_ + h];
    float aLi = g_CF[(7 * N_ + n) * H_ + h];

    float accr = 0.0f, acci = 0.0f;
    for (int c = 0; c < NCv; ++c) {
        int cc = (dir == 0) ? c : (NCv - 1 - c);
        float* p = g_S + (((size_t)(dir * BATCH + b) * NCv + cc) * 32) * H_ + h;
        float fr = p[(2 * n + 0) * H_];
        float fi = p[(2 * n + 1) * H_];
        p[(2 * n + 0) * H_] = accr;
        p[(2 * n + 1) * H_] = acci;
        float t = aLr * accr - aLi * acci + fr;
        acci = aLr * acci + aLi * accr + fi;
        accr = t;
    }
}

// ---------------------------------------------------------------------------
// Scan pass 2 (merged bwd+fwd): ybuf is column-private smem (no syncs).
// Writes gelu output as fat-K split rows into g_A3 (compact if ds).
// grid (3, NCv, B), block 256.
// ---------------------------------------------------------------------------
__global__ void scan_pass2(const float* __restrict__ X,
                           const float* __restrict__ Dv,
                           int L, int Lout, int ds) {
    __shared__ float ybuf[CL_][256];
    int h   = blockIdx.x * 256 + threadIdx.x;
    int c   = blockIdx.y;
    int NCv = gridDim.y;
    int b   = blockIdx.z;
    int tid = threadIdx.x;
    int lo  = c * CL_;

    float ar[N_], ai[N_];
#pragma unroll
    for (int n = 0; n < N_; ++n) {
        ar[n] = g_CF[(0 * N_ + n) * H_ + h];
        ai[n] = g_CF[(1 * N_ + n) * H_ + h];
    }

    // ---- backward half ----
    {
        float wr[N_], wi[N_], sr[N_], si[N_];
        const float* stp =
            g_S + (((size_t)(1 * BATCH + b) * NCv + c) * 32) * H_ + h;
#pragma unroll
        for (int n = 0; n < N_; ++n) {
            wr[n] = g_CF[(4 * N_ + n) * H_ + h];
            wi[n] = g_CF[(5 * N_ + n) * H_ + h];
            sr[n] = stp[(2 * n + 0) * H_];
            si[n] = stp[(2 * n + 1) * H_];
        }
        const float* xp = X + ((size_t)b * L + lo + CL_ - 1) * H_ + h;
        for (int p = lo + CL_ - 1; p >= lo; --p) {
            if (!ds || !(p & 1)) {
                float a0 = 0.0f, a1 = 0.0f;
#pragma unroll
                for (int n = 0; n < N_; ++n) {
                    a0 = fmaf(wr[n], sr[n], a0);
                    a1 = fmaf(wi[n], si[n], a1);
                }
                ybuf[p - lo][tid] = 2.0f * (a0 - a1);
            }
            float u = *xp; xp -= H_;
#pragma unroll
            for (int n = 0; n < N_; ++n) {
                float t = fmaf(ar[n], sr[n], fmaf(-ai[n], si[n], u));
                si[n] = fmaf(ar[n], si[n], ai[n] * sr[n]);
                sr[n] = t;
            }
        }
    }

    // ---- forward half ----
    {
        float wr[N_], wi[N_], sr[N_], si[N_];
        const float* stp =
            g_S + (((size_t)(0 * BATCH + b) * NCv + c) * 32) * H_ + h;
#pragma unroll
        for (int n = 0; n < N_; ++n) {
            wr[n] = g_CF[(2 * N_ + n) * H_ + h];
            wi[n] = g_CF[(3 * N_ + n) * H_ + h];
            sr[n] = stp[(2 * n + 0) * H_];
            si[n] = stp[(2 * n + 1) * H_];
        }
        float Dh = Dv[h];
        const float* xp = X + ((size_t)b * L + lo) * H_ + h;
        for (int l = lo; l < lo + CL_; ++l) {
            float u = *xp; xp += H_;
#pragma unroll
            for (int n = 0; n < N_; ++n) {
                float t = fmaf(ar[n], sr[n], fmaf(-ai[n], si[n], u));
                si[n] = fmaf(ar[n], si[n], ai[n] * sr[n]);
                sr[n] = t;
            }
            if (!ds || !(l & 1)) {
                float a0 = 0.0f, a1 = 0.0f;
#pragma unroll
                for (int n = 0; n < N_; ++n) {
                    a0 = fmaf(wr[n], sr[n], a0);
                    a1 = fmaf(wi[n], si[n], a1);
                }
                int lrow = ds ? (l >> 1) : l;
                size_t rr = (size_t)b * Lout + lrow;
                float yv = 2.0f * (a0 - a1) + ybuf[l - lo][tid] + Dh * u;
                yv = 0.5f * yv * (1.0f + erff(yv * 0.70710678118654752f));
                __nv_bfloat16 hi, lo2; split_bf16(yv, hi, lo2);
                __nv_bfloat16* dst = g_A3 + rr * K3;
                dst[h] = hi; dst[H_ + h] = lo2; dst[2 * H_ + h] = hi;
            }
        }
    }
}

// ---------------------------------------------------------------------------
// GLU + residual + LayerNorm
// ---------------------------------------------------------------------------
__global__ void glu_ln_kernel(const float* __restrict__ V,
                              const float* __restrict__ X,
                              const float* __restrict__ nw,
                              const float* __restrict__ nb,
                              float* __restrict__ out, int ds) {
    int row_out = blockIdx.x;
    int row_in  = ds ? row_out * 2 : row_out;
    const float* v = V + (size_t)row_out * (2 * H_);
    const float* x = X + (size_t)row_in * H_;
    int tid = threadIdx.x;

    float vals[3];
    float s = 0.0f, q = 0.0f;
#pragma unroll
    for (int t = 0; t < 3; ++t) {
        int j = tid + t * 256;
        float a = v[j];
        float g = v[j + H_];
        float z = a * (1.0f / (1.0f + expf(-g)));
        float xr = z + x[j];
        vals[t] = xr;
        s += xr;
        q += xr * xr;
    }
    __shared__ float sh[18];
    int lane = tid & 31, wid = tid >> 5;
#pragma unroll
    for (int o = 16; o; o >>= 1) {
        s += __shfl_xor_sync(0xffffffffu, s, o);
        q += __shfl_xor_sync(0xffffffffu, q, o);
    }
    if (lane == 0) { sh[wid] = s; sh[8 + wid] = q; }
    __syncthreads();
    if (tid == 0) {
        float S = 0.0f, Q = 0.0f;
#pragma unroll
        for (int i = 0; i < 8; ++i) { S += sh[i]; Q += sh[8 + i]; }
        float mu = S * (1.0f / H_);
        float var = Q * (1.0f / H_) - mu * mu;
        sh[16] = mu;
        sh[17] = rsqrtf(var + 1e-5f);
    }
    __syncthreads();
    float mu = sh[16], inv = sh[17];
#pragma unroll
    for (int t = 0; t < 3; ++t) {
        int j = tid + t * 256;
        out[(size_t)row_out * H_ + j] = (vals[t] - mu) * inv * nw[j] + nb[j];
    }
}

// ---------------------------------------------------------------------------
// Head
// ---------------------------------------------------------------------------
__global__ void head_kernel(const float* __restrict__ X,
                            const float* __restrict__ W,
                            const float* __restrict__ bb,
                            float* __restrict__ out) {
    int row = blockIdx.x;
    __shared__ float xs[H_];
    for (int j = threadIdx.x; j < H_; j += blockDim.x)
        xs[j] = X[(size_t)row * H_ + j];
    __syncthreads();
    int d = threadIdx.x;
    if (d < NOUTS) {
        float sum = bb[d];
#pragma unroll 4
        for (int k = 0; k < H_; ++k)
            sum = fmaf(xs[k], W[k * NOUTS + d], sum);
        out[(size_t)row * NOUTS + d] = sum;
    }
}

// ---------------------------------------------------------------------------
extern "C" void kernel_launch(void* const* d_in, const int* in_sizes, int n_in,
                              void* d_out, int out_size) {
    const float* x_raw      = (const float*)d_in[1];
    const float* enc_w1     = (const float*)d_in[3];
    const float* enc_b1     = (const float*)d_in[4];
    const float* enc_w2     = (const float*)d_in[5];
    const float* enc_b2     = (const float*)d_in[6];
    const float* log_dt     = (const float*)d_in[7];
    const float* log_A_real = (const float*)d_in[8];
    const float* A_imag     = (const float*)d_in[9];
    const float* C_ri       = (const float*)d_in[10];
    const float* Dv         = (const float*)d_in[11];
    const float* out_w      = (const float*)d_in[12];
    const float* out_b      = (const float*)d_in[13];
    const float* norm_w     = (const float*)d_in[14];
    const float* norm_b     = (const float*)d_in[15];
    const float* wout_w     = (const float*)d_in[16];
    const float* wout_b     = (const float*)d_in[17];

    float *gA, *gB, *gV;
    cudaGetSymbolAddress((void**)&gA,  g_A);
    cudaGetSymbolAddress((void**)&gB,  g_Bf);
    cudaGetSymbolAddress((void**)&gV,  g_V);
    __nv_bfloat16 *gA3, *gW3, *gW3e;
    cudaGetSymbolAddress((void**)&gA3,  g_A3);
    cudaGetSymbolAddress((void**)&gW3,  g_W3);
    cudaGetSymbolAddress((void**)&gW3e, g_W3e);

    cudaFuncSetAttribute(hmma_gemm_kernel,
                         cudaFuncAttributeMaxDynamicSharedMemorySize, GSMEM);

    // weight conversions (fat-K bf16 split)
    wconv_layers<<<(NLAYERS * 2 * H_ * H_) / 256, 256>>>(out_w);
    wconv_enc<<<dim3(H_ / 32, H_ / 32), dim3(32, 8)>>>(enc_w2);

    // encoder
    enc1_kernel<<<BATCH * LMAX, 256>>>(x_raw, enc_w1, enc_b1);
    hmma_gemm_kernel<<<dim3(H_ / 128, (BATCH * LMAX) / 128), 256, GSMEM>>>(
        gA3, gW3e, enc_b2, gA, H_);

    int Lcur = LMAX;
    float* cur = gA;
    float* nxt = gB;
    for (int i = 0; i < NLAYERS; ++i) {
        int ds   = (i <= 2) ? 1 : 0;
        int Lout = ds ? Lcur / 2 : Lcur;
        int NCv  = Lcur / CL_;
        int Mout = BATCH * Lout;

        coef_kernel<<<(H_ * N_) / 256, 256>>>(log_dt, log_A_real, A_imag,
                                              C_ri, i);
        scan_pass1<<<dim3(3, NCv, BATCH * 2), 256>>>(cur, Lcur);
        scan_fix<<<(2 * BATCH * H_ * N_) / 256, 256>>>(NCv);
        scan_pass2<<<dim3(3, NCv, BATCH), 256>>>(cur, Dv + i * H_,
                                                 Lcur, Lout, ds);
        hmma_gemm_kernel<<<dim3((2 * H_) / 128, Mout / 128), 256, GSMEM>>>(
            gA3, gW3 + (size_t)i * 2 * H_ * K3, out_b + (size_t)i * 2 * H_,
            gV, 2 * H_);
        glu_ln_kernel<<<Mout, 256>>>(gV, cur, norm_w + i * H_, norm_b + i * H_,
                                     nxt, ds);
        Lcur = Lout;
        float* tmp = cur; cur = nxt; nxt = tmp;
    }

    head_kernel<<<BATCH * Lcur, 128>>>(cur, wout_w, wout_b, (float*)d_out);
}

// round 6
// speedup vs baseline: 2.6953x; 1.0653x over previous
#include <cuda_runtime.h>
#include <cuda_bf16.h>
#include <math.h>
#include <stdint.h>

#define H_ 768
#define N_ 16
#define NLAYERS 6
#define NOUTS 38
#define BATCH 8
#define LMAX 2048
#define NCMAX 64         // max chunks per sequence (CL fixed at 32)
#define CL_ 32
#define K3 2304          // 3 * H_
#define NCH 36           // K3 / 64
#define NSTAGE 3
#define STAGE_BYTES 32768
#define GSMEM (NSTAGE * STAGE_BYTES)
#define CFSZ (8*N_*H_)

#define MAXACT (BATCH*LMAX*H_)

__device__ float g_A [MAXACT];
__device__ float g_Bf[MAXACT];
__device__ float g_V [BATCH*LMAX*2*H_];
__device__ float g_S [(size_t)2*BATCH*NCMAX*2*N_*H_];
__device__ float g_CF[NLAYERS*CFSZ];
__device__ __nv_bfloat16 g_A3 [(size_t)BATCH*LMAX*K3];   // fat-K activations
__device__ __nv_bfloat16 g_W3 [(size_t)NLAYERS*2*H_*K3]; // fat-K layer weights
__device__ __nv_bfloat16 g_W3e[(size_t)H_*K3];           // fat-K encoder w2^T

// ---------------------------------------------------------------------------
// helpers
// ---------------------------------------------------------------------------
__device__ __forceinline__ uint32_t smem_u32(const void* p) {
    uint32_t a;
    asm("{ .reg .u64 t; cvta.to.shared.u64 t, %1; cvt.u32.u64 %0, t; }"
        : "=r"(a) : "l"(p));
    return a;
}
__device__ __forceinline__ void ldm4(uint32_t* r, uint32_t addr) {
    asm volatile("ldmatrix.sync.aligned.m8n8.x4.shared.b16 {%0,%1,%2,%3}, [%4];"
                 : "=r"(r[0]), "=r"(r[1]), "=r"(r[2]), "=r"(r[3]) : "r"(addr));
}
__device__ __forceinline__ void mma16816(float* c, const uint32_t* a,
                                         const uint32_t* b) {
    asm volatile(
        "mma.sync.aligned.m16n8k16.row.col.f32.bf16.bf16.f32 "
        "{%0,%1,%2,%3}, {%4,%5,%6,%7}, {%8,%9}, {%0,%1,%2,%3};"
        : "+f"(c[0]), "+f"(c[1]), "+f"(c[2]), "+f"(c[3])
        : "r"(a[0]), "r"(a[1]), "r"(a[2]), "r"(a[3]), "r"(b[0]), "r"(b[1]));
}
__device__ __forceinline__ void cp16(uint32_t saddr, const void* g) {
    asm volatile("cp.async.cg.shared.global [%0], [%1], 16;"
                 :: "r"(saddr), "l"(g));
}
__device__ __forceinline__ void cp_commit() {
    asm volatile("cp.async.commit_group;" ::: "memory");
}
template <int Nw>
__device__ __forceinline__ void cp_wait() {
    asm volatile("cp.async.wait_group %0;" :: "n"(Nw) : "memory");
}
__device__ __forceinline__ void split_bf16(float x, __nv_bfloat16& hi,
                                           __nv_bfloat16& lo) {
    hi = __float2bfloat16(x);
    lo = __float2bfloat16(x - __bfloat162float(hi));
}

// ---------------------------------------------------------------------------
// HMMA bf16 GEMM, cp.async 3-stage pipeline.
// ---------------------------------------------------------------------------
__global__ void __launch_bounds__(256, 2)
hmma_gemm_kernel(const __nv_bfloat16* __restrict__ A3,
                 const __nv_bfloat16* __restrict__ B3,
                 const float* __restrict__ bias,
                 float* __restrict__ C, int Ncols) {
    extern __shared__ __align__(128) char smem[];
    const uint32_t sbase = smem_u32(smem);

    const int tid  = threadIdx.x;
    const int wid  = tid >> 5;
    const int lane = tid & 31;
    const int warp_m = wid >> 2;
    const int warp_n = wid & 3;
    const int m_base = warp_m * 64;
    const int n_base = warp_n * 32;

    const int m0 = blockIdx.y * 128;
    const int n0 = blockIdx.x * 128;
    const __nv_bfloat16* Ab = A3 + (size_t)m0 * K3;
    const __nv_bfloat16* Bb = B3 + (size_t)n0 * K3;

    const int st_row = tid >> 3;
    const int st_seg = tid & 7;
    uint32_t st_off[4];
#pragma unroll
    for (int i = 0; i < 4; ++i) {
        int r = st_row + i * 32;
        st_off[i] = (uint32_t)(r * 128 + ((st_seg ^ (r & 7)) * 16));
    }

    int rA[4], xA[4];
#pragma unroll
    for (int mt = 0; mt < 4; ++mt) {
        rA[mt] = m_base + mt * 16 + (lane & 15);
        xA[mt] = rA[mt] & 7;
    }
    const int uhA = lane >> 4;
    int rB[2], xB[2];
#pragma unroll
    for (int nt2 = 0; nt2 < 2; ++nt2) {
        rB[nt2] = n_base + nt2 * 16 + ((lane >> 4) << 3) + (lane & 7);
        xB[nt2] = rB[nt2] & 7;
    }
    const int uhB = (lane >> 3) & 1;

    float acc[4][4][4];
#pragma unroll
    for (int mt = 0; mt < 4; ++mt)
#pragma unroll
        for (int nt = 0; nt < 4; ++nt)
#pragma unroll
            for (int e = 0; e < 4; ++e) acc[mt][nt][e] = 0.0f;

#pragma unroll
    for (int s = 0; s < NSTAGE; ++s) {
        uint32_t sa = sbase + s * STAGE_BYTES;
        uint32_t sb = sa + 16384;
#pragma unroll
        for (int i = 0; i < 4; ++i) {
            int r = st_row + i * 32;
            cp16(sa + st_off[i], Ab + (size_t)r * K3 + s * 64 + st_seg * 8);
            cp16(sb + st_off[i], Bb + (size_t)r * K3 + s * 64 + st_seg * 8);
        }
        cp_commit();
    }

    for (int c = 0; c < NCH; ++c) {
        cp_wait<NSTAGE - 1>();
        __syncthreads();
        int buf = c % NSTAGE;
        uint32_t sa = sbase + buf * STAGE_BYTES;
        uint32_t sb = sa + 16384;
#pragma unroll
        for (int kk = 0; kk < 4; ++kk) {
            uint32_t af[4][4], bf[2][4];
#pragma unroll
            for (int mt = 0; mt < 4; ++mt)
                ldm4(af[mt], sa + (uint32_t)(rA[mt] * 128 +
                             (((kk * 2 + uhA) ^ xA[mt]) * 16)));
#pragma unroll
            for (int nt2 = 0; nt2 < 2; ++nt2)
                ldm4(bf[nt2], sb + (uint32_t)(rB[nt2] * 128 +
                              (((kk * 2 + uhB) ^ xB[nt2]) * 16)));
#pragma unroll
            for (int mt = 0; mt < 4; ++mt)
#pragma unroll
                for (int nt = 0; nt < 4; ++nt)
                    mma16816(acc[mt][nt], af[mt], &bf[nt >> 1][(nt & 1) * 2]);
        }
        __syncthreads();
        if (c + NSTAGE < NCH) {
#pragma unroll
            for (int i = 0; i < 4; ++i) {
                int r = st_row + i * 32;
                cp16(sa + st_off[i],
                     Ab + (size_t)r * K3 + (c + NSTAGE) * 64 + st_seg * 8);
                cp16(sb + st_off[i],
                     Bb + (size_t)r * K3 + (c + NSTAGE) * 64 + st_seg * 8);
            }
        }
        cp_commit();
    }

    const int gr = lane >> 2;
    const int gc = (lane & 3) * 2;
#pragma unroll
    for (int nt = 0; nt < 4; ++nt) {
        int ncol = n0 + n_base + nt * 8 + gc;
        float b0 = bias[ncol], b1 = bias[ncol + 1];
#pragma unroll
        for (int mt = 0; mt < 4; ++mt) {
            int mr = m0 + m_base + mt * 16 + gr;
            float2 v0 = make_float2(acc[mt][nt][0] + b0, acc[mt][nt][1] + b1);
            float2 v1 = make_float2(acc[mt][nt][2] + b0, acc[mt][nt][3] + b1);
            *(float2*)&C[(size_t)mr * Ncols + ncol] = v0;
            *(float2*)&C[(size_t)(mr + 8) * Ncols + ncol] = v1;
        }
    }
}

// ---------------------------------------------------------------------------
// Weight converters
// ---------------------------------------------------------------------------
__global__ void wconv_layers(const float* __restrict__ out_w) {
    size_t idx = (size_t)blockIdx.x * blockDim.x + threadIdx.x;
    int k = idx % H_;
    size_t nr = idx / H_;
    float w = out_w[idx];
    __nv_bfloat16 hi, lo; split_bf16(w, hi, lo);
    __nv_bfloat16* dst = g_W3 + nr * K3;
    dst[k] = hi; dst[H_ + k] = hi; dst[2 * H_ + k] = lo;
}

__global__ void wconv_enc(const float* __restrict__ w2) {
    __shared__ float t[32][33];
    int k0 = blockIdx.y * 32, n0 = blockIdx.x * 32;
    int tx = threadIdx.x;
#pragma unroll
    for (int i = threadIdx.y; i < 32; i += 8)
        t[i][tx] = w2[(size_t)(k0 + i) * H_ + n0 + tx];
    __syncthreads();
#pragma unroll
    for (int i = threadIdx.y; i < 32; i += 8) {
        float w = t[tx][i];
        __nv_bfloat16 hi, lo; split_bf16(w, hi, lo);
        __nv_bfloat16* dst = g_W3e + (size_t)(n0 + i) * K3;
        dst[k0 + tx] = hi; dst[H_ + k0 + tx] = hi; dst[2 * H_ + k0 + tx] = lo;
    }
}

// ---------------------------------------------------------------------------
// Encoder stage 1 -> fat-K split activations
// ---------------------------------------------------------------------------
__global__ void enc1_kernel(const float* __restrict__ xr,
                            const float* __restrict__ w1,
                            const float* __restrict__ b1) {
    int row = blockIdx.x;
    __shared__ float xs[8];
    if (threadIdx.x < 8) xs[threadIdx.x] = xr[(size_t)row * 8 + threadIdx.x];
    __syncthreads();
    __nv_bfloat16* dst = g_A3 + (size_t)row * K3;
    for (int j = threadIdx.x; j < H_; j += blockDim.x) {
        float s = b1[j];
#pragma unroll
        for (int k = 0; k < 8; ++k) s = fmaf(xs[k], w1[k * H_ + j], s);
        float v = s / (1.0f + fabsf(s));
        __nv_bfloat16 hi, lo; split_bf16(v, hi, lo);
        dst[j] = hi; dst[H_ + j] = lo; dst[2 * H_ + j] = hi;
    }
}

// ---------------------------------------------------------------------------
// SSM coefficients for ALL layers in one launch. grid ((H*N)/256, NLAYERS).
// ---------------------------------------------------------------------------
__global__ void coef_kernel(const float* __restrict__ log_dt,
                            const float* __restrict__ log_A_real,
                            const float* __restrict__ A_imag,
                            const float* __restrict__ C_ri) {
    int idx = blockIdx.x * blockDim.x + threadIdx.x;
    int layer = blockIdx.y;
    int h = idx % H_;
    int n = idx / H_;

    float dt  = expf(log_dt[layer * H_ + h]);
    int pidx  = (layer * H_ + h) * N_ + n;
    float Are = -expf(log_A_real[pidx]);
    float Aim = A_imag[pidx];
    float dr = dt * Are, di = dt * Aim;
    float e  = expf(dr);
    float ar = e * cosf(di);
    float ai = e * sinf(di);
    float invA2 = 1.0f / (Are * Are + Aim * Aim);
    float dBr = ((ar - 1.0f) * Are + ai * Aim) * invA2;
    float dBi = (ai * Are - (ar - 1.0f) * Aim) * invA2;

    size_t c0idx = ((((size_t)layer * 2 + 0) * H_ + h) * N_ + n) * 2;
    size_t c1idx = ((((size_t)layer * 2 + 1) * H_ + h) * N_ + n) * 2;
    float c0r = C_ri[c0idx], c0i = C_ri[c0idx + 1];
    float c1r = C_ri[c1idx], c1i = C_ri[c1idx + 1];

    float eL = expf(CL_ * dr);
    float* cf = g_CF + layer * CFSZ;
    cf[(0 * N_ + n) * H_ + h] = ar;
    cf[(1 * N_ + n) * H_ + h] = ai;
    cf[(2 * N_ + n) * H_ + h] = c0r * dBr - c0i * dBi;
    cf[(3 * N_ + n) * H_ + h] = c0r * dBi + c0i * dBr;
    cf[(4 * N_ + n) * H_ + h] = c1r * dBr - c1i * dBi;
    cf[(5 * N_ + n) * H_ + h] = c1r * dBi + c1i * dBr;
    cf[(6 * N_ + n) * H_ + h] = eL * cosf(CL_ * di);
    cf[(7 * N_ + n) * H_ + h] = eL * sinf(CL_ * di);
}

// ---------------------------------------------------------------------------
// Scan pass 1: per-chunk (CL=32) local final states, both directions.
// u load software-pipelined one step ahead.
// ---------------------------------------------------------------------------
__global__ void scan_pass1(const float* __restrict__ X, int L, int layer) {
    int h   = blockIdx.x * 256 + threadIdx.x;
    int c   = blockIdx.y;
    int NCv = gridDim.y;
    int bz  = blockIdx.z;
    int b   = bz >> 1;
    int dir = bz & 1;
    const float* cf = g_CF + layer * CFSZ;

    float ar[N_], ai[N_], sr[N_], si[N_];
#pragma unroll
    for (int n = 0; n < N_; ++n) {
        ar[n] = cf[(0 * N_ + n) * H_ + h];
        ai[n] = cf[(1 * N_ + n) * H_ + h];
        sr[n] = 0.0f; si[n] = 0.0f;
    }
    int lo = c * CL_;
    const float* xp = (dir == 0) ? X + ((size_t)b * L + lo) * H_ + h
                                 : X + ((size_t)b * L + lo + CL_ - 1) * H_ + h;
    int step = (dir == 0) ? H_ : -H_;
    float u = *xp;
#pragma unroll 4
    for (int l = 0; l < CL_; ++l) {
        xp += step;
        float un = (l < CL_ - 1) ? *xp : 0.0f;
#pragma unroll
        for (int n = 0; n < N_; ++n) {
            float t = fmaf(ar[n], sr[n], fmaf(-ai[n], si[n], u));
            si[n] = fmaf(ar[n], si[n], ai[n] * sr[n]);
            sr[n] = t;
        }
        u = un;
    }
    float* f = g_S + (((size_t)(dir * BATCH + b) * NCv + c) * 32) * H_ + h;
#pragma unroll
    for (int n = 0; n < N_; ++n) {
        f[(2 * n + 0) * H_] = sr[n];
        f[(2 * n + 1) * H_] = si[n];
    }
}

// ---------------------------------------------------------------------------
// Scan fix: serial chunk-state composition; finals -> init states.
// ---------------------------------------------------------------------------
__global__ void scan_fix(int NCv, int layer) {
    int idx = blockIdx.x * blockDim.x + threadIdx.x;
    int h   = idx % H_;
    int n   = (idx / H_) % N_;
    int b   = (idx / (H_ * N_)) % BATCH;
    int dir = idx / (H_ * N_ * BATCH);
    const float* cf = g_CF + layer * CFSZ;

    float aLr = cf[(6 * N_ + n) * H_ + h];
    float aLi = cf[(7 * N_ + n) * H_ + h];

    float accr = 0.0f, acci = 0.0f;
    for (int c = 0; c < NCv; ++c) {
        int cc = (dir == 0) ? c : (NCv - 1 - c);
        float* p = g_S + (((size_t)(dir * BATCH + b) * NCv + cc) * 32) * H_ + h;
        float fr = p[(2 * n + 0) * H_];
        float fi = p[(2 * n + 1) * H_];
        p[(2 * n + 0) * H_] = accr;
        p[(2 * n + 1) * H_] = acci;
        float t = aLr * accr - aLi * acci + fr;
        acci = aLr * acci + aLi * accr + fi;
        accr = t;
    }
}

// ---------------------------------------------------------------------------
// Scan pass 2 (merged bwd+fwd). ybuf/xbuf are column-private smem.
// bwd half loads X (pipelined) and caches it in xbuf; fwd half reads xbuf.
// ---------------------------------------------------------------------------
__global__ void scan_pass2(const float* __restrict__ X,
                           const float* __restrict__ Dv,
                           int L, int Lout, int ds, int layer) {
    __shared__ float ybuf[CL_][256];
    __shared__ float xbuf[CL_][256];
    int h   = blockIdx.x * 256 + threadIdx.x;
    int c   = blockIdx.y;
    int NCv = gridDim.y;
    int b   = blockIdx.z;
    int tid = threadIdx.x;
    int lo  = c * CL_;
    const float* cf = g_CF + layer * CFSZ;

    float ar[N_], ai[N_];
#pragma unroll
    for (int n = 0; n < N_; ++n) {
        ar[n] = cf[(0 * N_ + n) * H_ + h];
        ai[n] = cf[(1 * N_ + n) * H_ + h];
    }

    // ---- backward half ----
    {
        float wr[N_], wi[N_], sr[N_], si[N_];
        const float* stp =
            g_S + (((size_t)(1 * BATCH + b) * NCv + c) * 32) * H_ + h;
#pragma unroll
        for (int n = 0; n < N_; ++n) {
            wr[n] = cf[(4 * N_ + n) * H_ + h];
            wi[n] = cf[(5 * N_ + n) * H_ + h];
            sr[n] = stp[(2 * n + 0) * H_];
            si[n] = stp[(2 * n + 1) * H_];
        }
        const float* xp = X + ((size_t)b * L + lo + CL_ - 1) * H_ + h;
        float u = *xp;
        for (int k = CL_ - 1; k >= 0; --k) {
            xp -= H_;
            float un = (k > 0) ? *xp : 0.0f;
            int p = lo + k;
            if (!ds || !(p & 1)) {
                float a0 = 0.0f, a1 = 0.0f;
#pragma unroll
                for (int n = 0; n < N_; ++n) {
                    a0 = fmaf(wr[n], sr[n], a0);
                    a1 = fmaf(wi[n], si[n], a1);
                }
                ybuf[k][tid] = 2.0f * (a0 - a1);
            }
            xbuf[k][tid] = u;
#pragma unroll
            for (int n = 0; n < N_; ++n) {
                float t = fmaf(ar[n], sr[n], fmaf(-ai[n], si[n], u));
                si[n] = fmaf(ar[n], si[n], ai[n] * sr[n]);
                sr[n] = t;
            }
            u = un;
        }
    }

    // ---- forward half ----
    {
        float wr[N_], wi[N_], sr[N_], si[N_];
        const float* stp =
            g_S + (((size_t)(0 * BATCH + b) * NCv + c) * 32) * H_ + h;
#pragma unroll
        for (int n = 0; n < N_; ++n) {
            wr[n] = cf[(2 * N_ + n) * H_ + h];
            wi[n] = cf[(3 * N_ + n) * H_ + h];
            sr[n] = stp[(2 * n + 0) * H_];
            si[n] = stp[(2 * n + 1) * H_];
        }
        float Dh = Dv[h];
        for (int k = 0; k < CL_; ++k) {
            float u = xbuf[k][tid];
#pragma unroll
            for (int n = 0; n < N_; ++n) {
                float t = fmaf(ar[n], sr[n], fmaf(-ai[n], si[n], u));
                si[n] = fmaf(ar[n], si[n], ai[n] * sr[n]);
                sr[n] = t;
            }
            int l = lo + k;
            if (!ds || !(l & 1)) {
                float a0 = 0.0f, a1 = 0.0f;
#pragma unroll
                for (int n = 0; n < N_; ++n) {
                    a0 = fmaf(wr[n], sr[n], a0);
                    a1 = fmaf(wi[n], si[n], a1);
                }
                int lrow = ds ? (l >> 1) : l;
                size_t rr = (size_t)b * Lout + lrow;
                float yv = 2.0f * (a0 - a1) + ybuf[k][tid] + Dh * u;
                yv = 0.5f * yv * (1.0f + erff(yv * 0.70710678118654752f));
                __nv_bfloat16 hi, lo2; split_bf16(yv, hi, lo2);
                __nv_bfloat16* dst = g_A3 + rr * K3;
                dst[h] = hi; dst[H_ + h] = lo2; dst[2 * H_ + h] = hi;
            }
        }
    }
}

// ---------------------------------------------------------------------------
// GLU + residual + LayerNorm. 192 threads, float4 everywhere.
// ---------------------------------------------------------------------------
__global__ void glu_ln_kernel(const float* __restrict__ V,
                              const float* __restrict__ X,
                              const float* __restrict__ nw,
                              const float* __restrict__ nb,
                              float* __restrict__ out, int ds) {
    int row_out = blockIdx.x;
    int row_in  = ds ? row_out * 2 : row_out;
    const float4* v4 = (const float4*)(V + (size_t)row_out * (2 * H_));
    const float4* x4 = (const float4*)(X + (size_t)row_in * H_);
    int tid = threadIdx.x;   // 0..191

    float4 a = v4[tid];
    float4 g = v4[192 + tid];
    float4 x = x4[tid];
    float4 z;
    z.x = a.x / (1.0f + expf(-g.x)) + x.x;
    z.y = a.y / (1.0f + expf(-g.y)) + x.y;
    z.z = a.z / (1.0f + expf(-g.z)) + x.z;
    z.w = a.w / (1.0f + expf(-g.w)) + x.w;
    float s = z.x + z.y + z.z + z.w;
    float q = z.x * z.x + z.y * z.y + z.z * z.z + z.w * z.w;

    __shared__ float sh[14];
    int lane = tid & 31, wid = tid >> 5;   // 6 warps
#pragma unroll
    for (int o = 16; o; o >>= 1) {
        s += __shfl_xor_sync(0xffffffffu, s, o);
        q += __shfl_xor_sync(0xffffffffu, q, o);
    }
    if (lane == 0) { sh[wid] = s; sh[6 + wid] = q; }
    __syncthreads();
    if (tid == 0) {
        float S = 0.0f, Q = 0.0f;
#pragma unroll
        for (int i = 0; i < 6; ++i) { S += sh[i]; Q += sh[6 + i]; }
        float mu = S * (1.0f / H_);
        float var = Q * (1.0f / H_) - mu * mu;
        sh[12] = mu;
        sh[13] = rsqrtf(var + 1e-5f);
    }
    __syncthreads();
    float mu = sh[12], inv = sh[13];
    float4 w = ((const float4*)nw)[tid];
    float4 bb = ((const float4*)nb)[tid];
    float4 o;
    o.x = (z.x - mu) * inv * w.x + bb.x;
    o.y = (z.y - mu) * inv * w.y + bb.y;
    o.z = (z.z - mu) * inv * w.z + bb.z;
    o.w = (z.w - mu) * inv * w.w + bb.w;
    ((float4*)(out + (size_t)row_out * H_))[tid] = o;
}

// ---------------------------------------------------------------------------
// Head
// ---------------------------------------------------------------------------
__global__ void head_kernel(const float* __restrict__ X,
                            const float* __restrict__ W,
                            const float* __restrict__ bb,
                            float* __restrict__ out) {
    int row = blockIdx.x;
    __shared__ float xs[H_];
    for (int j = threadIdx.x; j < H_; j += blockDim.x)
        xs[j] = X[(size_t)row * H_ + j];
    __syncthreads();
    int d = threadIdx.x;
    if (d < NOUTS) {
        float sum = bb[d];
#pragma unroll 4
        for (int k = 0; k < H_; ++k)
            sum = fmaf(xs[k], W[k * NOUTS + d], sum);
        out[(size_t)row * NOUTS + d] = sum;
    }
}

// ---------------------------------------------------------------------------
extern "C" void kernel_launch(void* const* d_in, const int* in_sizes, int n_in,
                              void* d_out, int out_size) {
    const float* x_raw      = (const float*)d_in[1];
    const float* enc_w1     = (const float*)d_in[3];
    const float* enc_b1     = (const float*)d_in[4];
    const float* enc_w2     = (const float*)d_in[5];
    const float* enc_b2     = (const float*)d_in[6];
    const float* log_dt     = (const float*)d_in[7];
    const float* log_A_real = (const float*)d_in[8];
    const float* A_imag     = (const float*)d_in[9];
    const float* C_ri       = (const float*)d_in[10];
    const float* Dv         = (const float*)d_in[11];
    const float* out_w      = (const float*)d_in[12];
    const float* out_b      = (const float*)d_in[13];
    const float* norm_w     = (const float*)d_in[14];
    const float* norm_b     = (const float*)d_in[15];
    const float* wout_w     = (const float*)d_in[16];
    const float* wout_b     = (const float*)d_in[17];

    float *gA, *gB, *gV;
    cudaGetSymbolAddress((void**)&gA,  g_A);
    cudaGetSymbolAddress((void**)&gB,  g_Bf);
    cudaGetSymbolAddress((void**)&gV,  g_V);
    __nv_bfloat16 *gA3, *gW3, *gW3e;
    cudaGetSymbolAddress((void**)&gA3,  g_A3);
    cudaGetSymbolAddress((void**)&gW3,  g_W3);
    cudaGetSymbolAddress((void**)&gW3e, g_W3e);

    cudaFuncSetAttribute(hmma_gemm_kernel,
                         cudaFuncAttributeMaxDynamicSharedMemorySize, GSMEM);

    // upfront: weight conversions + all-layer coefficients
    wconv_layers<<<(NLAYERS * 2 * H_ * H_) / 256, 256>>>(out_w);
    wconv_enc<<<dim3(H_ / 32, H_ / 32), dim3(32, 8)>>>(enc_w2);
    coef_kernel<<<dim3((H_ * N_) / 256, NLAYERS), 256>>>(log_dt, log_A_real,
                                                         A_imag, C_ri);

    // encoder
    enc1_kernel<<<BATCH * LMAX, 256>>>(x_raw, enc_w1, enc_b1);
    hmma_gemm_kernel<<<dim3(H_ / 128, (BATCH * LMAX) / 128), 256, GSMEM>>>(
        gA3, gW3e, enc_b2, gA, H_);

    int Lcur = LMAX;
    float* cur = gA;
    float* nxt = gB;
    for (int i = 0; i < NLAYERS; ++i) {
        int ds   = (i <= 2) ? 1 : 0;
        int Lout = ds ? Lcur / 2 : Lcur;
        int NCv  = Lcur / CL_;
        int Mout = BATCH * Lout;

        scan_pass1<<<dim3(3, NCv, BATCH * 2), 256>>>(cur, Lcur, i);
        scan_fix<<<(2 * BATCH * H_ * N_) / 256, 256>>>(NCv, i);
        scan_pass2<<<dim3(3, NCv, BATCH), 256>>>(cur, Dv + i * H_,
                                                 Lcur, Lout, ds, i);
        hmma_gemm_kernel<<<dim3((2 * H_) / 128, Mout / 128), 256, GSMEM>>>(
            gA3, gW3 + (size_t)i * 2 * H_ * K3, out_b + (size_t)i * 2 * H_,
            gV, 2 * H_);
        glu_ln_kernel<<<Mout, 192>>>(gV, cur, norm_w + i * H_, norm_b + i * H_,
                                     nxt, ds);
        Lcur = Lout;
        float* tmp = cur; cur = nxt; nxt = tmp;
    }

    head_kernel<<<BATCH * Lcur, 128>>>(cur, wout_w, wout_b, (float*)d_out);
}

// round 7
// speedup vs baseline: 2.8354x; 1.0520x over previous
#include <cuda_runtime.h>
#include <cuda_bf16.h>
#include <math.h>
#include <stdint.h>

#define H_ 768
#define N_ 16
#define NLAYERS 6
#define NOUTS 38
#define BATCH 8
#define LMAX 2048
#define NCMAX 64
#define CL_ 32
#define K3 2304          // 3 * H_
#define NCH 36           // K3 / 64
#define NSTAGE 3
#define STAGE_BYTES 32768
#define GSMEM (NSTAGE * STAGE_BYTES)
#define CFSZ (8*N_*H_)

#define MAXACT (BATCH*LMAX*H_)

__device__ float g_A [MAXACT];
__device__ float g_Bf[MAXACT];
__device__ float g_V [BATCH*LMAX*2*H_];
__device__ float g_S [(size_t)2*BATCH*NCMAX*2*N_*H_];
__device__ float g_CF[NLAYERS*CFSZ];
__device__ __nv_bfloat16 g_A3 [(size_t)BATCH*LMAX*K3];
__device__ __nv_bfloat16 g_W3 [(size_t)NLAYERS*2*H_*K3];
__device__ __nv_bfloat16 g_W3e[(size_t)H_*K3];

// ---------------------------------------------------------------------------
// helpers
// ---------------------------------------------------------------------------
__device__ __forceinline__ uint32_t smem_u32(const void* p) {
    uint32_t a;
    asm("{ .reg .u64 t; cvta.to.shared.u64 t, %1; cvt.u32.u64 %0, t; }"
        : "=r"(a) : "l"(p));
    return a;
}
__device__ __forceinline__ void ldm4(uint32_t* r, uint32_t addr) {
    asm volatile("ldmatrix.sync.aligned.m8n8.x4.shared.b16 {%0,%1,%2,%3}, [%4];"
                 : "=r"(r[0]), "=r"(r[1]), "=r"(r[2]), "=r"(r[3]) : "r"(addr));
}
__device__ __forceinline__ void mma16816(float* c, const uint32_t* a,
                                         const uint32_t* b) {
    asm volatile(
        "mma.sync.aligned.m16n8k16.row.col.f32.bf16.bf16.f32 "
        "{%0,%1,%2,%3}, {%4,%5,%6,%7}, {%8,%9}, {%0,%1,%2,%3};"
        : "+f"(c[0]), "+f"(c[1]), "+f"(c[2]), "+f"(c[3])
        : "r"(a[0]), "r"(a[1]), "r"(a[2]), "r"(a[3]), "r"(b[0]), "r"(b[1]));
}
__device__ __forceinline__ void cp16(uint32_t saddr, const void* g) {
    asm volatile("cp.async.cg.shared.global [%0], [%1], 16;"
                 :: "r"(saddr), "l"(g));
}
__device__ __forceinline__ void cp_commit() {
    asm volatile("cp.async.commit_group;" ::: "memory");
}
template <int Nw>
__device__ __forceinline__ void cp_wait() {
    asm volatile("cp.async.wait_group %0;" :: "n"(Nw) : "memory");
}
__device__ __forceinline__ void split_bf16(float x, __nv_bfloat16& hi,
                                           __nv_bfloat16& lo) {
    hi = __float2bfloat16(x);
    lo = __float2bfloat16(x - __bfloat162float(hi));
}
__device__ __forceinline__ __nv_bfloat162 pack2(__nv_bfloat16 a,
                                                __nv_bfloat16 b) {
    __nv_bfloat162 r; r.x = a; r.y = b; return r;
}

// ---------------------------------------------------------------------------
// HMMA bf16 GEMM, cp.async 3-stage pipeline, ONE sync per K-chunk.
// C[M,N] = A3[M,K3] @ B3[N,K3]^T + bias[N]
// ---------------------------------------------------------------------------
__global__ void __launch_bounds__(256, 2)
hmma_gemm_kernel(const __nv_bfloat16* __restrict__ A3,
                 const __nv_bfloat16* __restrict__ B3,
                 const float* __restrict__ bias,
                 float* __restrict__ C, int Ncols) {
    extern __shared__ __align__(128) char smem[];
    const uint32_t sbase = smem_u32(smem);

    const int tid  = threadIdx.x;
    const int wid  = tid >> 5;
    const int lane = tid & 31;
    const int warp_m = wid >> 2;
    const int warp_n = wid & 3;
    const int m_base = warp_m * 64;
    const int n_base = warp_n * 32;

    const int m0 = blockIdx.y * 128;
    const int n0 = blockIdx.x * 128;
    const __nv_bfloat16* Ab = A3 + (size_t)m0 * K3;
    const __nv_bfloat16* Bb = B3 + (size_t)n0 * K3;

    const int st_row = tid >> 3;
    const int st_seg = tid & 7;
    uint32_t st_off[4];
#pragma unroll
    for (int i = 0; i < 4; ++i) {
        int r = st_row + i * 32;
        st_off[i] = (uint32_t)(r * 128 + ((st_seg ^ (r & 7)) * 16));
    }

    int rA[4], xA[4];
#pragma unroll
    for (int mt = 0; mt < 4; ++mt) {
        rA[mt] = m_base + mt * 16 + (lane & 15);
        xA[mt] = rA[mt] & 7;
    }
    const int uhA = lane >> 4;
    int rB[2], xB[2];
#pragma unroll
    for (int nt2 = 0; nt2 < 2; ++nt2) {
        rB[nt2] = n_base + nt2 * 16 + ((lane >> 4) << 3) + (lane & 7);
        xB[nt2] = rB[nt2] & 7;
    }
    const int uhB = (lane >> 3) & 1;

    float acc[4][4][4];
#pragma unroll
    for (int mt = 0; mt < 4; ++mt)
#pragma unroll
        for (int nt = 0; nt < 4; ++nt)
#pragma unroll
            for (int e = 0; e < 4; ++e) acc[mt][nt][e] = 0.0f;

    // prologue: stages 0..NSTAGE-2
#pragma unroll
    for (int s = 0; s < NSTAGE - 1; ++s) {
        uint32_t sa = sbase + s * STAGE_BYTES;
        uint32_t sb = sa + 16384;
#pragma unroll
        for (int i = 0; i < 4; ++i) {
            int r = st_row + i * 32;
            cp16(sa + st_off[i], Ab + (size_t)r * K3 + s * 64 + st_seg * 8);
            cp16(sb + st_off[i], Bb + (size_t)r * K3 + s * 64 + st_seg * 8);
        }
        cp_commit();
    }

    for (int c = 0; c < NCH; ++c) {
        cp_wait<NSTAGE - 2>();
        __syncthreads();                 // all warps done with buf (c-1)%NSTAGE
        int pf = c + NSTAGE - 1;
        if (pf < NCH) {
            uint32_t sa = sbase + (pf % NSTAGE) * STAGE_BYTES;
            uint32_t sb = sa + 16384;
#pragma unroll
            for (int i = 0; i < 4; ++i) {
                int r = st_row + i * 32;
                cp16(sa + st_off[i], Ab + (size_t)r * K3 + pf * 64 + st_seg * 8);
                cp16(sb + st_off[i], Bb + (size_t)r * K3 + pf * 64 + st_seg * 8);
            }
        }
        cp_commit();

        uint32_t sa = sbase + (c % NSTAGE) * STAGE_BYTES;
        uint32_t sb = sa + 16384;
#pragma unroll
        for (int kk = 0; kk < 4; ++kk) {
            uint32_t af[4][4], bf[2][4];
#pragma unroll
            for (int mt = 0; mt < 4; ++mt)
                ldm4(af[mt], sa + (uint32_t)(rA[mt] * 128 +
                             (((kk * 2 + uhA) ^ xA[mt]) * 16)));
#pragma unroll
            for (int nt2 = 0; nt2 < 2; ++nt2)
                ldm4(bf[nt2], sb + (uint32_t)(rB[nt2] * 128 +
                              (((kk * 2 + uhB) ^ xB[nt2]) * 16)));
#pragma unroll
            for (int mt = 0; mt < 4; ++mt)
#pragma unroll
                for (int nt = 0; nt < 4; ++nt)
                    mma16816(acc[mt][nt], af[mt], &bf[nt >> 1][(nt & 1) * 2]);
        }
    }

    const int gr = lane >> 2;
    const int gc = (lane & 3) * 2;
#pragma unroll
    for (int nt = 0; nt < 4; ++nt) {
        int ncol = n0 + n_base + nt * 8 + gc;
        float b0 = bias[ncol], b1 = bias[ncol + 1];
#pragma unroll
        for (int mt = 0; mt < 4; ++mt) {
            int mr = m0 + m_base + mt * 16 + gr;
            float2 v0 = make_float2(acc[mt][nt][0] + b0, acc[mt][nt][1] + b1);
            float2 v1 = make_float2(acc[mt][nt][2] + b0, acc[mt][nt][3] + b1);
            *(float2*)&C[(size_t)mr * Ncols + ncol] = v0;
            *(float2*)&C[(size_t)(mr + 8) * Ncols + ncol] = v1;
        }
    }
}

// ---------------------------------------------------------------------------
// Weight converters: pairwise, bf162 stores. A3=[hi|lo|hi], W3=[hi|hi|lo]
// ---------------------------------------------------------------------------
__global__ void wconv_layers(const float* __restrict__ out_w) {
    size_t idx = (size_t)blockIdx.x * blockDim.x + threadIdx.x;  // pair index
    int kp = idx % (H_ / 2);
    size_t nr = idx / (H_ / 2);
    int j = kp * 2;
    float2 w = *(const float2*)&out_w[nr * H_ + j];
    __nv_bfloat16 h0, l0, h1, l1;
    split_bf16(w.x, h0, l0);
    split_bf16(w.y, h1, l1);
    __nv_bfloat16* dst = g_W3 + nr * K3;
    *(__nv_bfloat162*)&dst[j]          = pack2(h0, h1);
    *(__nv_bfloat162*)&dst[H_ + j]     = pack2(h0, h1);
    *(__nv_bfloat162*)&dst[2 * H_ + j] = pack2(l0, l1);
}

__global__ void wconv_enc(const float* __restrict__ w2) {
    __shared__ float t[32][33];
    int k0 = blockIdx.y * 32, n0 = blockIdx.x * 32;
    int tx = threadIdx.x;
#pragma unroll
    for (int i = threadIdx.y; i < 32; i += 8)
        t[i][tx] = w2[(size_t)(k0 + i) * H_ + n0 + tx];
    __syncthreads();
#pragma unroll
    for (int i = threadIdx.y; i < 32; i += 8) {
        float w = t[tx][i];
        __nv_bfloat16 hi, lo; split_bf16(w, hi, lo);
        __nv_bfloat16* dst = g_W3e + (size_t)(n0 + i) * K3;
        dst[k0 + tx] = hi; dst[H_ + k0 + tx] = hi; dst[2 * H_ + k0 + tx] = lo;
    }
}

// ---------------------------------------------------------------------------
// Encoder stage 1 -> fat-K split, pairwise bf162 stores. 192 threads.
// ---------------------------------------------------------------------------
__global__ void enc1_kernel(const float* __restrict__ xr,
                            const float* __restrict__ w1,
                            const float* __restrict__ b1) {
    int row = blockIdx.x;
    __shared__ float xs[8];
    if (threadIdx.x < 8) xs[threadIdx.x] = xr[(size_t)row * 8 + threadIdx.x];
    __syncthreads();
    __nv_bfloat16* dst = g_A3 + (size_t)row * K3;
#pragma unroll
    for (int p = threadIdx.x; p < H_ / 2; p += 192) {
        int j = p * 2;
        float2 bv = *(const float2*)&b1[j];
        float s0 = bv.x, s1 = bv.y;
#pragma unroll
        for (int k = 0; k < 8; ++k) {
            float2 wv = *(const float2*)&w1[k * H_ + j];
            s0 = fmaf(xs[k], wv.x, s0);
            s1 = fmaf(xs[k], wv.y, s1);
        }
        float v0 = s0 / (1.0f + fabsf(s0));
        float v1 = s1 / (1.0f + fabsf(s1));
        __nv_bfloat16 h0, l0, h1, l1;
        split_bf16(v0, h0, l0);
        split_bf16(v1, h1, l1);
        *(__nv_bfloat162*)&dst[j]          = pack2(h0, h1);
        *(__nv_bfloat162*)&dst[H_ + j]     = pack2(l0, l1);
        *(__nv_bfloat162*)&dst[2 * H_ + j] = pack2(h0, h1);
    }
}

// ---------------------------------------------------------------------------
// SSM coefficients, all layers in one launch.
// ---------------------------------------------------------------------------
__global__ void coef_kernel(const float* __restrict__ log_dt,
                            const float* __restrict__ log_A_real,
                            const float* __restrict__ A_imag,
                            const float* __restrict__ C_ri) {
    int idx = blockIdx.x * blockDim.x + threadIdx.x;
    int layer = blockIdx.y;
    int h = idx % H_;
    int n = idx / H_;

    float dt  = expf(log_dt[layer * H_ + h]);
    int pidx  = (layer * H_ + h) * N_ + n;
    float Are = -expf(log_A_real[pidx]);
    float Aim = A_imag[pidx];
    float dr = dt * Are, di = dt * Aim;
    float e  = expf(dr);
    float ar = e * cosf(di);
    float ai = e * sinf(di);
    float invA2 = 1.0f / (Are * Are + Aim * Aim);
    float dBr = ((ar - 1.0f) * Are + ai * Aim) * invA2;
    float dBi = (ai * Are - (ar - 1.0f) * Aim) * invA2;

    size_t c0idx = ((((size_t)layer * 2 + 0) * H_ + h) * N_ + n) * 2;
    size_t c1idx = ((((size_t)layer * 2 + 1) * H_ + h) * N_ + n) * 2;
    float c0r = C_ri[c0idx], c0i = C_ri[c0idx + 1];
    float c1r = C_ri[c1idx], c1i = C_ri[c1idx + 1];

    float eL = expf(CL_ * dr);
    float* cf = g_CF + layer * CFSZ;
    cf[(0 * N_ + n) * H_ + h] = ar;
    cf[(1 * N_ + n) * H_ + h] = ai;
    cf[(2 * N_ + n) * H_ + h] = c0r * dBr - c0i * dBi;
    cf[(3 * N_ + n) * H_ + h] = c0r * dBi + c0i * dBr;
    cf[(4 * N_ + n) * H_ + h] = c1r * dBr - c1i * dBi;
    cf[(5 * N_ + n) * H_ + h] = c1r * dBi + c1i * dBr;
    cf[(6 * N_ + n) * H_ + h] = eL * cosf(CL_ * di);
    cf[(7 * N_ + n) * H_ + h] = eL * sinf(CL_ * di);
}

// ---------------------------------------------------------------------------
// Scan pass 1: BOTH directions in one block, X staged once in smem.
// grid (3, NCv, B), block 256. Column-private xbuf -> no syncs needed.
// ---------------------------------------------------------------------------
__global__ void scan_pass1(const float* __restrict__ X, int L, int layer) {
    __shared__ float xbuf[CL_][256];
    int h   = blockIdx.x * 256 + threadIdx.x;
    int c   = blockIdx.y;
    int NCv = gridDim.y;
    int b   = blockIdx.z;
    int tid = threadIdx.x;
    int lo  = c * CL_;
    const float* cf = g_CF + layer * CFSZ;

    const float* xp = X + ((size_t)b * L + lo) * H_ + h;
#pragma unroll
    for (int k = 0; k < CL_; ++k)
        xbuf[k][tid] = xp[(size_t)k * H_];

    float ar[N_], ai[N_], sr[N_], si[N_];
#pragma unroll
    for (int n = 0; n < N_; ++n) {
        ar[n] = cf[(0 * N_ + n) * H_ + h];
        ai[n] = cf[(1 * N_ + n) * H_ + h];
        sr[n] = 0.0f; si[n] = 0.0f;
    }
    // forward
#pragma unroll 4
    for (int k = 0; k < CL_; ++k) {
        float u = xbuf[k][tid];
#pragma unroll
        for (int n = 0; n < N_; ++n) {
            float t = fmaf(ar[n], sr[n], fmaf(-ai[n], si[n], u));
            si[n] = fmaf(ar[n], si[n], ai[n] * sr[n]);
            sr[n] = t;
        }
    }
    float* f0 = g_S + (((size_t)(0 * BATCH + b) * NCv + c) * 32) * H_ + h;
#pragma unroll
    for (int n = 0; n < N_; ++n) {
        f0[(2 * n + 0) * H_] = sr[n];
        f0[(2 * n + 1) * H_] = si[n];
        sr[n] = 0.0f; si[n] = 0.0f;
    }
    // backward
#pragma unroll 4
    for (int k = CL_ - 1; k >= 0; --k) {
        float u = xbuf[k][tid];
#pragma unroll
        for (int n = 0; n < N_; ++n) {
            float t = fmaf(ar[n], sr[n], fmaf(-ai[n], si[n], u));
            si[n] = fmaf(ar[n], si[n], ai[n] * sr[n]);
            sr[n] = t;
        }
    }
    float* f1 = g_S + (((size_t)(1 * BATCH + b) * NCv + c) * 32) * H_ + h;
#pragma unroll
    for (int n = 0; n < N_; ++n) {
        f1[(2 * n + 0) * H_] = sr[n];
        f1[(2 * n + 1) * H_] = si[n];
    }
}

// ---------------------------------------------------------------------------
// Scan fix: serial chunk-state composition; finals -> init states.
// ---------------------------------------------------------------------------
__global__ void scan_fix(int NCv, int layer) {
    int idx = blockIdx.x * blockDim.x + threadIdx.x;
    int h   = idx % H_;
    int n   = (idx / H_) % N_;
    int b   = (idx / (H_ * N_)) % BATCH;
    int dir = idx / (H_ * N_ * BATCH);
    const float* cf = g_CF + layer * CFSZ;

    float aLr = cf[(6 * N_ + n) * H_ + h];
    float aLi = cf[(7 * N_ + n) * H_ + h];

    float accr = 0.0f, acci = 0.0f;
    for (int c = 0; c < NCv; ++c) {
        int cc = (dir == 0) ? c : (NCv - 1 - c);
        float* p = g_S + (((size_t)(dir * BATCH + b) * NCv + cc) * 32) * H_ + h;
        float fr = p[(2 * n + 0) * H_];
        float fi = p[(2 * n + 1) * H_];
        p[(2 * n + 0) * H_] = accr;
        p[(2 * n + 1) * H_] = acci;
        float t = aLr * accr - aLi * acci + fr;
        acci = aLr * acci + aLi * accr + fi;
        accr = t;
    }
}

// ---------------------------------------------------------------------------
// Scan pass 2 (merged bwd+fwd). ybuf/xbuf column-private smem.
// ---------------------------------------------------------------------------
__global__ void scan_pass2(const float* __restrict__ X,
                           const float* __restrict__ Dv,
                           int L, int Lout, int ds, int layer) {
    __shared__ float ybuf[CL_][256];
    __shared__ float xbuf[CL_][256];
    int h   = blockIdx.x * 256 + threadIdx.x;
    int c   = blockIdx.y;
    int NCv = gridDim.y;
    int b   = blockIdx.z;
    int tid = threadIdx.x;
    int lo  = c * CL_;
    const float* cf = g_CF + layer * CFSZ;

    const float* xp0 = X + ((size_t)b * L + lo) * H_ + h;
#pragma unroll
    for (int k = 0; k < CL_; ++k)
        xbuf[k][tid] = xp0[(size_t)k * H_];

    float ar[N_], ai[N_];
#pragma unroll
    for (int n = 0; n < N_; ++n) {
        ar[n] = cf[(0 * N_ + n) * H_ + h];
        ai[n] = cf[(1 * N_ + n) * H_ + h];
    }

    // ---- backward half ----
    {
        float wr[N_], wi[N_], sr[N_], si[N_];
        const float* stp =
            g_S + (((size_t)(1 * BATCH + b) * NCv + c) * 32) * H_ + h;
#pragma unroll
        for (int n = 0; n < N_; ++n) {
            wr[n] = cf[(4 * N_ + n) * H_ + h];
            wi[n] = cf[(5 * N_ + n) * H_ + h];
            sr[n] = stp[(2 * n + 0) * H_];
            si[n] = stp[(2 * n + 1) * H_];
        }
        for (int k = CL_ - 1; k >= 0; --k) {
            int p = lo + k;
            if (!ds || !(p & 1)) {
                float a0 = 0.0f, a1 = 0.0f;
#pragma unroll
                for (int n = 0; n < N_; ++n) {
                    a0 = fmaf(wr[n], sr[n], a0);
                    a1 = fmaf(wi[n], si[n], a1);
                }
                ybuf[k][tid] = 2.0f * (a0 - a1);
            }
            float u = xbuf[k][tid];
#pragma unroll
            for (int n = 0; n < N_; ++n) {
                float t = fmaf(ar[n], sr[n], fmaf(-ai[n], si[n], u));
                si[n] = fmaf(ar[n], si[n], ai[n] * sr[n]);
                sr[n] = t;
            }
        }
    }

    // ---- forward half ----
    {
        float wr[N_], wi[N_], sr[N_], si[N_];
        const float* stp =
            g_S + (((size_t)(0 * BATCH + b) * NCv + c) * 32) * H_ + h;
#pragma unroll
        for (int n = 0; n < N_; ++n) {
            wr[n] = cf[(2 * N_ + n) * H_ + h];
            wi[n] = cf[(3 * N_ + n) * H_ + h];
            sr[n] = stp[(2 * n + 0) * H_];
            si[n] = stp[(2 * n + 1) * H_];
        }
        float Dh = Dv[h];
        for (int k = 0; k < CL_; ++k) {
            float u = xbuf[k][tid];
#pragma unroll
            for (int n = 0; n < N_; ++n) {
                float t = fmaf(ar[n], sr[n], fmaf(-ai[n], si[n], u));
                si[n] = fmaf(ar[n], si[n], ai[n] * sr[n]);
                sr[n] = t;
            }
            int l = lo + k;
            if (!ds || !(l & 1)) {
                float a0 = 0.0f, a1 = 0.0f;
#pragma unroll
                for (int n = 0; n < N_; ++n) {
                    a0 = fmaf(wr[n], sr[n], a0);
                    a1 = fmaf(wi[n], si[n], a1);
                }
                int lrow = ds ? (l >> 1) : l;
                size_t rr = (size_t)b * Lout + lrow;
                float yv = 2.0f * (a0 - a1) + ybuf[k][tid] + Dh * u;
                yv = 0.5f * yv * (1.0f + erff(yv * 0.70710678118654752f));
                __nv_bfloat16 hi, lo2; split_bf16(yv, hi, lo2);
                __nv_bfloat16* dst = g_A3 + rr * K3;
                dst[h] = hi; dst[H_ + h] = lo2; dst[2 * H_ + h] = hi;
            }
        }
    }
}

// ---------------------------------------------------------------------------
// GLU + residual + LayerNorm. 192 threads, float4.
// ---------------------------------------------------------------------------
__global__ void glu_ln_kernel(const float* __restrict__ V,
                              const float* __restrict__ X,
                              const float* __restrict__ nw,
                              const float* __restrict__ nb,
                              float* __restrict__ out, int ds) {
    int row_out = blockIdx.x;
    int row_in  = ds ? row_out * 2 : row_out;
    const float4* v4 = (const float4*)(V + (size_t)row_out * (2 * H_));
    const float4* x4 = (const float4*)(X + (size_t)row_in * H_);
    int tid = threadIdx.x;

    float4 a = v4[tid];
    float4 g = v4[192 + tid];
    float4 x = x4[tid];
    float4 z;
    z.x = a.x / (1.0f + expf(-g.x)) + x.x;
    z.y = a.y / (1.0f + expf(-g.y)) + x.y;
    z.z = a.z / (1.0f + expf(-g.z)) + x.z;
    z.w = a.w / (1.0f + expf(-g.w)) + x.w;
    float s = z.x + z.y + z.z + z.w;
    float q = z.x * z.x + z.y * z.y + z.z * z.z + z.w * z.w;

    __shared__ float sh[14];
    int lane = tid & 31, wid = tid >> 5;
#pragma unroll
    for (int o = 16; o; o >>= 1) {
        s += __shfl_xor_sync(0xffffffffu, s, o);
        q += __shfl_xor_sync(0xffffffffu, q, o);
    }
    if (lane == 0) { sh[wid] = s; sh[6 + wid] = q; }
    __syncthreads();
    if (tid == 0) {
        float S = 0.0f, Q = 0.0f;
#pragma unroll
        for (int i = 0; i < 6; ++i) { S += sh[i]; Q += sh[6 + i]; }
        float mu = S * (1.0f / H_);
        float var = Q * (1.0f / H_) - mu * mu;
        sh[12] = mu;
        sh[13] = rsqrtf(var + 1e-5f);
    }
    __syncthreads();
    float mu = sh[12], inv = sh[13];
    float4 w = ((const float4*)nw)[tid];
    float4 bb = ((const float4*)nb)[tid];
    float4 o;
    o.x = (z.x - mu) * inv * w.x + bb.x;
    o.y = (z.y - mu) * inv * w.y + bb.y;
    o.z = (z.z - mu) * inv * w.z + bb.z;
    o.w = (z.w - mu) * inv * w.w + bb.w;
    ((float4*)(out + (size_t)row_out * H_))[tid] = o;
}

// ---------------------------------------------------------------------------
// Head
// ---------------------------------------------------------------------------
__global__ void head_kernel(const float* __restrict__ X,
                            const float* __restrict__ W,
                            const float* __restrict__ bb,
                            float* __restrict__ out) {
    int row = blockIdx.x;
    __shared__ float xs[H_];
    for (int j = threadIdx.x; j < H_; j += blockDim.x)
        xs[j] = X[(size_t)row * H_ + j];
    __syncthreads();
    int d = threadIdx.x;
    if (d < NOUTS) {
        float sum = bb[d];
#pragma unroll 4
        for (int k = 0; k < H_; ++k)
            sum = fmaf(xs[k], W[k * NOUTS + d], sum);
        out[(size_t)row * NOUTS + d] = sum;
    }
}

// ---------------------------------------------------------------------------
extern "C" void kernel_launch(void* const* d_in, const int* in_sizes, int n_in,
                              void* d_out, int out_size) {
    const float* x_raw      = (const float*)d_in[1];
    const float* enc_w1     = (const float*)d_in[3];
    const float* enc_b1     = (const float*)d_in[4];
    const float* enc_w2     = (const float*)d_in[5];
    const float* enc_b2     = (const float*)d_in[6];
    const float* log_dt     = (const float*)d_in[7];
    const float* log_A_real = (const float*)d_in[8];
    const float* A_imag     = (const float*)d_in[9];
    const float* C_ri       = (const float*)d_in[10];
    const float* Dv         = (const float*)d_in[11];
    const float* out_w      = (const float*)d_in[12];
    const float* out_b      = (const float*)d_in[13];
    const float* norm_w     = (const float*)d_in[14];
    const float* norm_b     = (const float*)d_in[15];
    const float* wout_w     = (const float*)d_in[16];
    const float* wout_b     = (const float*)d_in[17];

    float *gA, *gB, *gV;
    cudaGetSymbolAddress((void**)&gA,  g_A);
    cudaGetSymbolAddress((void**)&gB,  g_Bf);
    cudaGetSymbolAddress((void**)&gV,  g_V);
    __nv_bfloat16 *gA3, *gW3, *gW3e;
    cudaGetSymbolAddress((void**)&gA3,  g_A3);
    cudaGetSymbolAddress((void**)&gW3,  g_W3);
    cudaGetSymbolAddress((void**)&gW3e, g_W3e);

    cudaFuncSetAttribute(hmma_gemm_kernel,
                         cudaFuncAttributeMaxDynamicSharedMemorySize, GSMEM);

    wconv_layers<<<(NLAYERS * 2 * H_ * (H_ / 2)) / 256, 256>>>(out_w);
    wconv_enc<<<dim3(H_ / 32, H_ / 32), dim3(32, 8)>>>(enc_w2);
    coef_kernel<<<dim3((H_ * N_) / 256, NLAYERS), 256>>>(log_dt, log_A_real,
                                                         A_imag, C_ri);

    enc1_kernel<<<BATCH * LMAX, 192>>>(x_raw, enc_w1, enc_b1);
    hmma_gemm_kernel<<<dim3(H_ / 128, (BATCH * LMAX) / 128), 256, GSMEM>>>(
        gA3, gW3e, enc_b2, gA, H_);

    int Lcur = LMAX;
    float* cur = gA;
    float* nxt = gB;
    for (int i = 0; i < NLAYERS; ++i) {
        int ds   = (i <= 2) ? 1 : 0;
        int Lout = ds ? Lcur / 2 : Lcur;
        int NCv  = Lcur / CL_;
        int Mout = BATCH * Lout;

        scan_pass1<<<dim3(3, NCv, BATCH), 256>>>(cur, Lcur, i);
        scan_fix<<<(2 * BATCH * H_ * N_) / 256, 256>>>(NCv, i);
        scan_pass2<<<dim3(3, NCv, BATCH), 256>>>(cur, Dv + i * H_,
                                                 Lcur, Lout, ds, i);
        hmma_gemm_kernel<<<dim3((2 * H_) / 128, Mout / 128), 256, GSMEM>>>(
            gA3, gW3 + (size_t)i * 2 * H_ * K3, out_b + (size_t)i * 2 * H_,
            gV, 2 * H_);
        glu_ln_kernel<<<Mout, 192>>>(gV, cur, norm_w + i * H_, norm_b + i * H_,
                                     nxt, ds);
        Lcur = Lout;
        float* tmp = cur; cur = nxt; nxt = tmp;
    }

    head_kernel<<<BATCH * Lcur, 128>>>(cur, wout_w, wout_b, (float*)d_out);
}